// round 7
// baseline (speedup 1.0000x reference)
#include <cuda_runtime.h>
#include <cstdint>

#define Bsz   4
#define Cc    256
#define CE    64
#define Tt    16
#define Hh    56
#define Ww    56
#define HW    3136
#define THW   50176
#define Gg    4
#define K2G   196
#define KPAD  224
#define EPSI  1e-5f

// Scratch (device globals: allocation-free rule)
__device__ float    g_xenc[(size_t)Bsz * CE * THW];
__device__ uint32_t g_xcorrt[(size_t)Bsz * THW * KPAD];   // [pixel][k'] tf32 bits (k<196 valid)
__device__ uint32_t g_dwt[Cc * KPAD];                     // dec_w permuted+rounded (padded)
__device__ uint32_t g_wt[CE * Cc];                        // enc_w rounded

__device__ __forceinline__ void cp_async16(uint32_t smem_addr, const void* gptr, int src_bytes) {
    asm volatile("cp.async.cg.shared.global [%0], [%1], 16, %2;"
                 :: "r"(smem_addr), "l"(gptr), "r"(src_bytes));
}
__device__ __forceinline__ void cp_commit() { asm volatile("cp.async.commit_group;"); }
__device__ __forceinline__ void cp_wait0()  { asm volatile("cp.async.wait_group 0;"); }
__device__ __forceinline__ void cp_wait1()  { asm volatile("cp.async.wait_group 1;"); }
__device__ __forceinline__ void cp_wait2()  { asm volatile("cp.async.wait_group 2;"); }

__device__ __forceinline__ uint32_t tf32rna(float f) {
    uint32_t r; asm("cvt.rna.tf32.f32 %0, %1;" : "=r"(r) : "f"(f)); return r;
}
__device__ __forceinline__ uint32_t smem_u32(const void* p) {
    return (uint32_t)__cvta_generic_to_shared(p);
}
__device__ __forceinline__ void mma_tf32(float* c, const uint32_t* a, const uint32_t* b) {
    asm volatile(
        "mma.sync.aligned.m16n8k8.row.col.f32.tf32.tf32.f32 "
        "{%0,%1,%2,%3}, {%4,%5,%6,%7}, {%8,%9}, {%0,%1,%2,%3};"
        : "+f"(c[0]), "+f"(c[1]), "+f"(c[2]), "+f"(c[3])
        : "r"(a[0]), "r"(a[1]), "r"(a[2]), "r"(a[3]), "r"(b[0]), "r"(b[1]));
}
__device__ __forceinline__ int swoff(int r, int k) {
    return r * 32 + ((((k >> 2) ^ r) & 7) << 2) + (k & 3);
}

// ---------------------------------------------------------------------------
// Kernel 0: prep
// ---------------------------------------------------------------------------
__global__ void prep_kernel(const float* __restrict__ dw, const float* __restrict__ ew)
{
    int idx = blockIdx.x * 256 + threadIdx.x;
    if (idx < Cc * KPAD) {
        int m = idx / KPAD, kp = idx % KPAD;
        uint32_t v = 0;
        if (kp < K2G) {
            int g = kp / 49, tap = kp % 49;
            v = tf32rna(dw[m * K2G + tap * 4 + g]);
        }
        g_dwt[idx] = v;
    } else if (idx < Cc * KPAD + CE * Cc) {
        int j = idx - Cc * KPAD;
        g_wt[j] = tf32rna(ew[j]);
    }
}

// ---------------------------------------------------------------------------
// Kernel 1: enc 1x1 conv on mma.sync tf32 (unchanged from R6)
// ---------------------------------------------------------------------------
#define E_SMEM (2 * (8192 + 32768))
#define E_AST(s) ((s) * 8192)
#define E_BST(s) (16384 + (s) * 32768)

__global__ void __launch_bounds__(256, 2) enc_kernel(
    const float* __restrict__ x,
    const float* __restrict__ eg, const float* __restrict__ eb,
    const float* __restrict__ em, const float* __restrict__ ev)
{
    extern __shared__ char esm[];
    const int t = threadIdx.x;
    const int wid = t >> 5, lane = t & 31;
    const int warpN = wid;
    const int n0 = blockIdx.x * 256;
    const int b  = blockIdx.y;

    const float* xb = x + (size_t)b * Cc * THW;

    float cacc[4][4][4];
    #pragma unroll
    for (int i = 0; i < 4; i++)
        #pragma unroll
        for (int j = 0; j < 4; j++)
            #pragma unroll
            for (int r = 0; r < 4; r++) cacc[i][j][r] = 0.f;

    int bpos[4];
    #pragma unroll
    for (int nt = 0; nt < 4; nt++) {
        int n = warpN * 32 + nt * 8 + (lane >> 2);
        bpos[nt] = (((n >> 2) ^ (2 * (lane & 3))) << 2) + (n & 3);
    }

    auto load_chunk = [&](int kc, int s) {
        {
            int e = t, r = e >> 3, c = e & 7;
            cp_async16(smem_u32(esm + E_AST(s) + r * 128 + (((c ^ r) & 7) << 4)),
                       g_wt + r * Cc + kc * 32 + c * 4, 16);
            e = t + 256; r = e >> 3; c = e & 7;
            cp_async16(smem_u32(esm + E_AST(s) + r * 128 + (((c ^ r) & 7) << 4)),
                       g_wt + r * Cc + kc * 32 + c * 4, 16);
        }
        #pragma unroll
        for (int i = 0; i < 8; i++) {
            int e = t + 256 * i;
            int k = e >> 6, j = e & 63;
            uint32_t dst = smem_u32(esm + E_BST(s) + k * 1024
                                    + ((j ^ (2 * (k & 3))) << 4));
            cp_async16(dst, xb + (size_t)(kc * 32 + k) * THW + n0 + j * 4, 16);
        }
    };

    load_chunk(0, 0);
    cp_commit();

    for (int c = 0; c < 8; c++) {
        const int s = c & 1;
        if (c > 0) __syncthreads();
        if (c + 1 < 8) { load_chunk(c + 1, s ^ 1); cp_commit(); cp_wait1(); }
        else cp_wait0();
        __syncthreads();

        const uint32_t* Ab = reinterpret_cast<const uint32_t*>(esm + E_AST(s));
        const uint32_t* Bb = reinterpret_cast<const uint32_t*>(esm + E_BST(s));

        #pragma unroll
        for (int ks = 0; ks < 4; ks++) {
            const int kf = ks * 8 + (lane & 3);
            uint32_t bfr[4][2];
            #pragma unroll
            for (int nt = 0; nt < 4; nt++) {
                bfr[nt][0] = tf32rna(__uint_as_float(Bb[kf * 256 + bpos[nt]]));
                bfr[nt][1] = tf32rna(__uint_as_float(Bb[(kf + 4) * 256 + bpos[nt]]));
            }
            #pragma unroll
            for (int mt = 0; mt < 4; mt++) {
                int r = mt * 16 + (lane >> 2);
                uint32_t afr[4];
                afr[0] = Ab[swoff(r,     kf)];
                afr[1] = Ab[swoff(r + 8, kf)];
                afr[2] = Ab[swoff(r,     kf + 4)];
                afr[3] = Ab[swoff(r + 8, kf + 4)];
                #pragma unroll
                for (int nt = 0; nt < 4; nt++)
                    mma_tf32(cacc[mt][nt], afr, bfr[nt]);
            }
        }
    }

    #pragma unroll
    for (int mt = 0; mt < 4; mt++) {
        int ce0 = mt * 16 + (lane >> 2);
        float inv0  = eg[ce0] * rsqrtf(ev[ce0] + EPSI);
        float bias0 = eb[ce0] - em[ce0] * inv0;
        float inv1  = eg[ce0 + 8] * rsqrtf(ev[ce0 + 8] + EPSI);
        float bias1 = eb[ce0 + 8] - em[ce0 + 8] * inv1;
        float* op0 = g_xenc + ((size_t)b * CE + ce0)     * THW + n0;
        float* op1 = g_xenc + ((size_t)b * CE + ce0 + 8) * THW + n0;
        #pragma unroll
        for (int nt = 0; nt < 4; nt++) {
            int n = warpN * 32 + nt * 8 + (lane & 3) * 2;
            float2 o0, o1;
            o0.x = fmaxf(cacc[mt][nt][0] * inv0 + bias0, 0.f);
            o0.y = fmaxf(cacc[mt][nt][1] * inv0 + bias0, 0.f);
            o1.x = fmaxf(cacc[mt][nt][2] * inv1 + bias1, 0.f);
            o1.y = fmaxf(cacc[mt][nt][3] * inv1 + bias1, 0.f);
            *reinterpret_cast<float2*>(op0 + n) = o0;
            *reinterpret_cast<float2*>(op1 + n) = o1;
        }
    }
}

// ---------------------------------------------------------------------------
// Kernel 2: corr v2 — sliding-window, 7 px/thread, ky-outer, x2 ring buffer.
// Block 64 thr: r = tid>>3 (0..7 rows), q = tid&7, px0 = q*7.
// Grid (7 h-tiles of 8 rows, 16 t, 16 b*4+g). All 16 ch resident.
// smem (floats): x1s[16][8][56] @0, x2r[16][8][64] @7168,
//                wsm[16][52] @15360, stg[3136] @16192  -> 77312 B
// ---------------------------------------------------------------------------
#define C_SMEM 77312
#define X1S(ce, r, px)   ((ce) * 448 + (r) * 56 + (px))
#define X2R(ce, s, col)  (7168 + (ce) * 512 + (s) * 64 + (col))
#define WSM(ce, tap)     (15360 + (ce) * 52 + (tap))
#define STG(j)           (16192 + (j))

__global__ void __launch_bounds__(64) corr_kernel(const float* __restrict__ fw)
{
    extern __shared__ float cs[];
    const int tid = threadIdx.x;
    const int r   = tid >> 3;
    const int q   = tid & 7;
    const int px0 = q * 7;

    const int h0 = blockIdx.x * 8;
    const int tt = blockIdx.y;
    const int b  = blockIdx.z >> 2;
    const int g  = blockIdx.z & 3;
    const int ce0 = g * 16;

    const int t1 = (tt == 0) ? 0 : tt - 1;
    const float* x1base = g_xenc + (size_t)b * CE * THW + (size_t)t1 * HW;
    const float* x2base = g_xenc + (size_t)b * CE * THW + (size_t)tt * HW;

    // ---- fill weights: 16 x 49 ----
    for (int i = tid; i < 16 * 49; i += 64) {
        int ce = i / 49, tap = i % 49;
        cs[WSM(ce, tap)] = fw[((size_t)(ce0 + ce) * Tt + tt) * 49 + tap];
    }
    // ---- fill x1: 16 x 8 x 56 ----
    for (int i = tid; i < 16 * 448; i += 64) {
        int ce = i / 448, rem = i % 448;
        int rr = rem / 56, px = rem % 56;
        cs[X1S(ce, rr, px)] = x1base[(size_t)(ce0 + ce) * THW + (h0 + rr) * Ww + px];
    }
    // ---- prefill x2 ring: rows h0-3 .. h0+4 ----
    for (int hg = h0 - 3; hg <= h0 + 4; hg++) {
        int slot = (hg + 8) & 7;
        bool rowok = (hg >= 0 && hg < Hh);
        for (int i = tid; i < 16 * 62; i += 64) {
            int ce = i / 62, c = i % 62;
            int wx = c - 3;
            float v = 0.f;
            if (rowok && wx >= 0 && wx < Ww)
                v = x2base[(size_t)(ce0 + ce) * THW + hg * Ww + wx];
            cs[X2R(ce, slot, c)] = v;
        }
    }
    __syncthreads();

    const size_t pixbase = (size_t)b * THW + (size_t)tt * HW + (size_t)h0 * Ww;

    #pragma unroll 1
    for (int ky = 0; ky < 7; ky++) {
        // ---- compute: acc[kx][p] over 16 channels ----
        float acc[7][7];
        #pragma unroll
        for (int kx = 0; kx < 7; kx++)
            #pragma unroll
            for (int p = 0; p < 7; p++) acc[kx][p] = 0.f;

        const int slot = (h0 + r + ky + 5) & 7;   // == (h0+r+ky-3+8)&7

        #pragma unroll 4
        for (int ce = 0; ce < 16; ce++) {
            float y[7], z[13], wv[7];
            #pragma unroll
            for (int p = 0; p < 7; p++) y[p] = cs[X1S(ce, r, px0 + p)];
            #pragma unroll
            for (int j = 0; j < 13; j++) z[j] = cs[X2R(ce, slot, px0 + j)];
            #pragma unroll
            for (int k = 0; k < 7; k++) wv[k] = cs[WSM(ce, ky * 7 + k)];
            #pragma unroll
            for (int kx = 0; kx < 7; kx++)
                #pragma unroll
                for (int p = 0; p < 7; p++)
                    acc[kx][p] += wv[kx] * (y[p] * z[p + kx]);
        }

        // ---- stage (conflict-free: 8r+17q distinct mod 32) ----
        #pragma unroll
        for (int p = 0; p < 7; p++)
            #pragma unroll
            for (int kx = 0; kx < 7; kx++)
                cs[STG((r * 56 + px0 + p) * 7 + kx)] = acc[kx][p] * (1.f / 16.f);
        __syncthreads();

        // ---- store: coalesced islands of 7 floats per pixel ----
        {
            uint32_t* gb = g_xcorrt + (size_t)g * 49 + (size_t)ky * 7;
            for (int i = tid; i < 3136; i += 64) {
                int pl = i / 7, kx = i % 7;
                gb[(pixbase + pl) * KPAD + kx] = __float_as_uint(cs[STG(i)]);
            }
        }
        // ---- load next ring row (slot of h0+ky-3, now free) ----
        if (ky + 1 < 7) {
            int hg = h0 + ky + 5;
            int slotn = (hg + 8) & 7;
            bool rowok = (hg < Hh);
            for (int i = tid; i < 16 * 62; i += 64) {
                int ce = i / 62, c = i % 62;
                int wx = c - 3;
                float v = 0.f;
                if (rowok && wx >= 0 && wx < Ww)
                    v = x2base[(size_t)(ce0 + ce) * THW + hg * Ww + wx];
                cs[X2R(ce, slotn, c)] = v;
            }
        }
        __syncthreads();
    }
}

// ---------------------------------------------------------------------------
// Kernel 3: dec GEMM, BM=256 x BN=128, 512 thr = 16 warps (4m x 4n),
// warp tile 64x32, 3-stage cp.async, zero-fill k>=196 via src_bytes predicate.
// ---------------------------------------------------------------------------
#define D_SMEM (3 * (32768 + 16384))
#define D_AST(s) ((s) * 32768)
#define D_BST(s) (98304 + (s) * 16384)

__global__ void __launch_bounds__(512, 1) dec_kernel(
    const float* __restrict__ x,
    const float* __restrict__ dg, const float* __restrict__ db,
    const float* __restrict__ dm, const float* __restrict__ dv,
    float* __restrict__ out)
{
    extern __shared__ char dsm[];
    const int t = threadIdx.x;
    const int wid = t >> 5, lane = t & 31;
    const int warpM = wid >> 2;            // 0..3 (64 m each)
    const int warpN = wid & 3;             // 0..3 (32 n each)

    const int nx = blockIdx.x;             // 392 n-tiles of 128
    const int b  = blockIdx.y;

    const uint32_t* brow = g_xcorrt + ((size_t)b * THW + (size_t)nx * 128) * KPAD;

    float cacc[4][4][4];
    #pragma unroll
    for (int i = 0; i < 4; i++)
        #pragma unroll
        for (int j = 0; j < 4; j++)
            #pragma unroll
            for (int rr = 0; rr < 4; rr++) cacc[i][j][rr] = 0.f;

    auto load_chunk = [&](int kc, int s) {
        #pragma unroll
        for (int i = 0; i < 4; i++) {      // A: 256 rows x 8 chunks = 2048
            int e = t + 512 * i;
            int rr = e >> 3, c = e & 7;
            cp_async16(smem_u32(dsm + D_AST(s) + rr * 128 + (((c ^ rr) & 7) << 4)),
                       g_dwt + (size_t)rr * KPAD + kc * 32 + c * 4, 16);
        }
        #pragma unroll
        for (int i = 0; i < 2; i++) {      // B: 128 rows x 8 chunks = 1024
            int e = t + 512 * i;
            int rr = e >> 3, c = e & 7;
            int sz = (kc * 8 + c < 49) ? 16 : 0;   // k>=196 zero-fill
            cp_async16(smem_u32(dsm + D_BST(s) + rr * 128 + (((c ^ rr) & 7) << 4)),
                       brow + (size_t)rr * KPAD + kc * 32 + c * 4, sz);
        }
    };

    load_chunk(0, 0); cp_commit();
    load_chunk(1, 1); cp_commit();

    for (int c = 0; c < 7; c++) {
        const int s = c % 3;
        if (c > 0) __syncthreads();
        if (c + 2 < 7) { load_chunk(c + 2, (c + 2) % 3); cp_commit(); }
        if (c < 5) cp_wait2(); else if (c == 5) cp_wait1(); else cp_wait0();
        __syncthreads();

        const uint32_t* Ab = reinterpret_cast<const uint32_t*>(dsm + D_AST(s));
        const uint32_t* Bb = reinterpret_cast<const uint32_t*>(dsm + D_BST(s));

        #pragma unroll
        for (int ks = 0; ks < 4; ks++) {
            const int kf = ks * 8 + (lane & 3);
            uint32_t bfr[4][2];
            #pragma unroll
            for (int nt = 0; nt < 4; nt++) {
                int n = warpN * 32 + nt * 8 + (lane >> 2);
                bfr[nt][0] = Bb[swoff(n, kf)];
                bfr[nt][1] = Bb[swoff(n, kf + 4)];
            }
            #pragma unroll
            for (int mt = 0; mt < 4; mt++) {
                int rr = warpM * 64 + mt * 16 + (lane >> 2);
                uint32_t afr[4];
                afr[0] = Ab[swoff(rr,     kf)];
                afr[1] = Ab[swoff(rr + 8, kf)];
                afr[2] = Ab[swoff(rr,     kf + 4)];
                afr[3] = Ab[swoff(rr + 8, kf + 4)];
                #pragma unroll
                for (int nt = 0; nt < 4; nt++)
                    mma_tf32(cacc[mt][nt], afr, bfr[nt]);
            }
        }
    }

    const size_t nbase = (size_t)nx * 128;
    #pragma unroll
    for (int mt = 0; mt < 4; mt++) {
        int mrow = warpM * 64 + mt * 16 + (lane >> 2);
        float inv0  = dg[mrow] * rsqrtf(dv[mrow] + EPSI);
        float bias0 = db[mrow] - dm[mrow] * inv0;
        float inv1  = dg[mrow + 8] * rsqrtf(dv[mrow + 8] + EPSI);
        float bias1 = db[mrow + 8] - dm[mrow + 8] * inv1;
        const float* xr0 = x   + ((size_t)b * Cc + mrow)     * THW + nbase;
        const float* xr1 = x   + ((size_t)b * Cc + mrow + 8) * THW + nbase;
        float*       op0 = out + ((size_t)b * Cc + mrow)     * THW + nbase;
        float*       op1 = out + ((size_t)b * Cc + mrow + 8) * THW + nbase;
        #pragma unroll
        for (int nt = 0; nt < 4; nt++) {
            int n = warpN * 32 + nt * 8 + (lane & 3) * 2;
            float2 r0 = *reinterpret_cast<const float2*>(xr0 + n);
            float2 r1 = *reinterpret_cast<const float2*>(xr1 + n);
            float2 o0, o1;
            o0.x = fmaxf(cacc[mt][nt][0] * inv0 + bias0 + r0.x, 0.f);
            o0.y = fmaxf(cacc[mt][nt][1] * inv0 + bias0 + r0.y, 0.f);
            o1.x = fmaxf(cacc[mt][nt][2] * inv1 + bias1 + r1.x, 0.f);
            o1.y = fmaxf(cacc[mt][nt][3] * inv1 + bias1 + r1.y, 0.f);
            *reinterpret_cast<float2*>(op0 + n) = o0;
            *reinterpret_cast<float2*>(op1 + n) = o1;
        }
    }
}

// ---------------------------------------------------------------------------
extern "C" void kernel_launch(void* const* d_in, const int* in_sizes, int n_in,
                              void* d_out, int out_size)
{
    const float* x     = (const float*)d_in[0];
    const float* enc_w = (const float*)d_in[1];
    const float* eg    = (const float*)d_in[2];
    const float* eb    = (const float*)d_in[3];
    const float* em    = (const float*)d_in[4];
    const float* ev    = (const float*)d_in[5];
    const float* fw    = (const float*)d_in[6];
    const float* dw    = (const float*)d_in[7];
    const float* dg    = (const float*)d_in[8];
    const float* db    = (const float*)d_in[9];
    const float* dm    = (const float*)d_in[10];
    const float* dv    = (const float*)d_in[11];
    float* out = (float*)d_out;

    cudaFuncSetAttribute(enc_kernel,
                         cudaFuncAttributeMaxDynamicSharedMemorySize, E_SMEM);
    cudaFuncSetAttribute(corr_kernel,
                         cudaFuncAttributeMaxDynamicSharedMemorySize, C_SMEM);
    cudaFuncSetAttribute(dec_kernel,
                         cudaFuncAttributeMaxDynamicSharedMemorySize, D_SMEM);

    int prep_n = Cc * KPAD + CE * Cc;
    prep_kernel<<<(prep_n + 255) / 256, 256>>>(dw, enc_w);

    dim3 g1(THW / 256, Bsz);
    enc_kernel<<<g1, 256, E_SMEM>>>(x, eg, eb, em, ev);

    dim3 g2(Hh / 8, Tt, Bsz * Gg);
    corr_kernel<<<g2, 64, C_SMEM>>>(fw);

    dim3 g3(THW / 128, Bsz);
    dec_kernel<<<g3, 512, D_SMEM>>>(x, dg, db, dm, dv, out);
}

// round 8
// speedup vs baseline: 1.4810x; 1.4810x over previous
#include <cuda_runtime.h>
#include <cstdint>

#define Bsz   4
#define Cc    256
#define CE    64
#define Tt    16
#define Hh    56
#define Ww    56
#define HW    3136
#define THW   50176
#define Gg    4
#define K2G   196
#define KPAD  224
#define EPSI  1e-5f

// Scratch (device globals: allocation-free rule)
__device__ float    g_xenc[(size_t)Bsz * CE * THW];
__device__ uint32_t g_xcorrt[(size_t)Bsz * THW * KPAD];   // [pixel][k'] tf32 bits
__device__ uint32_t g_dwt[Cc * KPAD];                     // dec_w permuted+rounded
__device__ uint32_t g_wt[CE * Cc];                        // enc_w rounded

__device__ __forceinline__ void cp_async16(uint32_t smem_addr, const void* gptr, int src_bytes) {
    asm volatile("cp.async.cg.shared.global [%0], [%1], 16, %2;"
                 :: "r"(smem_addr), "l"(gptr), "r"(src_bytes));
}
__device__ __forceinline__ void cp_commit() { asm volatile("cp.async.commit_group;"); }
__device__ __forceinline__ void cp_wait0()  { asm volatile("cp.async.wait_group 0;"); }
__device__ __forceinline__ void cp_wait1()  { asm volatile("cp.async.wait_group 1;"); }
__device__ __forceinline__ void cp_wait2()  { asm volatile("cp.async.wait_group 2;"); }

__device__ __forceinline__ uint32_t tf32rna(float f) {
    uint32_t r; asm("cvt.rna.tf32.f32 %0, %1;" : "=r"(r) : "f"(f)); return r;
}
__device__ __forceinline__ uint32_t smem_u32(const void* p) {
    return (uint32_t)__cvta_generic_to_shared(p);
}
__device__ __forceinline__ void mma_tf32(float* c, const uint32_t* a, const uint32_t* b) {
    asm volatile(
        "mma.sync.aligned.m16n8k8.row.col.f32.tf32.tf32.f32 "
        "{%0,%1,%2,%3}, {%4,%5,%6,%7}, {%8,%9}, {%0,%1,%2,%3};"
        : "+f"(c[0]), "+f"(c[1]), "+f"(c[2]), "+f"(c[3])
        : "r"(a[0]), "r"(a[1]), "r"(a[2]), "r"(a[3]), "r"(b[0]), "r"(b[1]));
}
__device__ __forceinline__ int swoff(int r, int k) {
    return r * 32 + ((((k >> 2) ^ r) & 7) << 2) + (k & 3);
}

// ---------------------------------------------------------------------------
// Kernel 0: prep
// ---------------------------------------------------------------------------
__global__ void prep_kernel(const float* __restrict__ dw, const float* __restrict__ ew)
{
    int idx = blockIdx.x * 256 + threadIdx.x;
    if (idx < Cc * KPAD) {
        int m = idx / KPAD, kp = idx % KPAD;
        uint32_t v = 0;
        if (kp < K2G) {
            int g = kp / 49, tap = kp % 49;
            v = tf32rna(dw[m * K2G + tap * 4 + g]);
        }
        g_dwt[idx] = v;
    } else if (idx < Cc * KPAD + CE * Cc) {
        int j = idx - Cc * KPAD;
        g_wt[j] = tf32rna(ew[j]);
    }
}

// ---------------------------------------------------------------------------
// Kernel 1: enc 1x1 conv on mma.sync tf32 (unchanged, measured ~75us)
// ---------------------------------------------------------------------------
#define E_SMEM (2 * (8192 + 32768))
#define E_AST(s) ((s) * 8192)
#define E_BST(s) (16384 + (s) * 32768)

__global__ void __launch_bounds__(256, 2) enc_kernel(
    const float* __restrict__ x,
    const float* __restrict__ eg, const float* __restrict__ eb,
    const float* __restrict__ em, const float* __restrict__ ev)
{
    extern __shared__ char esm[];
    const int t = threadIdx.x;
    const int wid = t >> 5, lane = t & 31;
    const int warpN = wid;
    const int n0 = blockIdx.x * 256;
    const int b  = blockIdx.y;

    const float* xb = x + (size_t)b * Cc * THW;

    float cacc[4][4][4];
    #pragma unroll
    for (int i = 0; i < 4; i++)
        #pragma unroll
        for (int j = 0; j < 4; j++)
            #pragma unroll
            for (int r = 0; r < 4; r++) cacc[i][j][r] = 0.f;

    int bpos[4];
    #pragma unroll
    for (int nt = 0; nt < 4; nt++) {
        int n = warpN * 32 + nt * 8 + (lane >> 2);
        bpos[nt] = (((n >> 2) ^ (2 * (lane & 3))) << 2) + (n & 3);
    }

    auto load_chunk = [&](int kc, int s) {
        {
            int e = t, r = e >> 3, c = e & 7;
            cp_async16(smem_u32(esm + E_AST(s) + r * 128 + (((c ^ r) & 7) << 4)),
                       g_wt + r * Cc + kc * 32 + c * 4, 16);
            e = t + 256; r = e >> 3; c = e & 7;
            cp_async16(smem_u32(esm + E_AST(s) + r * 128 + (((c ^ r) & 7) << 4)),
                       g_wt + r * Cc + kc * 32 + c * 4, 16);
        }
        #pragma unroll
        for (int i = 0; i < 8; i++) {
            int e = t + 256 * i;
            int k = e >> 6, j = e & 63;
            uint32_t dst = smem_u32(esm + E_BST(s) + k * 1024
                                    + ((j ^ (2 * (k & 3))) << 4));
            cp_async16(dst, xb + (size_t)(kc * 32 + k) * THW + n0 + j * 4, 16);
        }
    };

    load_chunk(0, 0);
    cp_commit();

    for (int c = 0; c < 8; c++) {
        const int s = c & 1;
        if (c > 0) __syncthreads();
        if (c + 1 < 8) { load_chunk(c + 1, s ^ 1); cp_commit(); cp_wait1(); }
        else cp_wait0();
        __syncthreads();

        const uint32_t* Ab = reinterpret_cast<const uint32_t*>(esm + E_AST(s));
        const uint32_t* Bb = reinterpret_cast<const uint32_t*>(esm + E_BST(s));

        #pragma unroll
        for (int ks = 0; ks < 4; ks++) {
            const int kf = ks * 8 + (lane & 3);
            uint32_t bfr[4][2];
            #pragma unroll
            for (int nt = 0; nt < 4; nt++) {
                bfr[nt][0] = tf32rna(__uint_as_float(Bb[kf * 256 + bpos[nt]]));
                bfr[nt][1] = tf32rna(__uint_as_float(Bb[(kf + 4) * 256 + bpos[nt]]));
            }
            #pragma unroll
            for (int mt = 0; mt < 4; mt++) {
                int r = mt * 16 + (lane >> 2);
                uint32_t afr[4];
                afr[0] = Ab[swoff(r,     kf)];
                afr[1] = Ab[swoff(r + 8, kf)];
                afr[2] = Ab[swoff(r,     kf + 4)];
                afr[3] = Ab[swoff(r + 8, kf + 4)];
                #pragma unroll
                for (int nt = 0; nt < 4; nt++)
                    mma_tf32(cacc[mt][nt], afr, bfr[nt]);
            }
        }
    }

    #pragma unroll
    for (int mt = 0; mt < 4; mt++) {
        int ce0 = mt * 16 + (lane >> 2);
        float inv0  = eg[ce0] * rsqrtf(ev[ce0] + EPSI);
        float bias0 = eb[ce0] - em[ce0] * inv0;
        float inv1  = eg[ce0 + 8] * rsqrtf(ev[ce0 + 8] + EPSI);
        float bias1 = eb[ce0 + 8] - em[ce0 + 8] * inv1;
        float* op0 = g_xenc + ((size_t)b * CE + ce0)     * THW + n0;
        float* op1 = g_xenc + ((size_t)b * CE + ce0 + 8) * THW + n0;
        #pragma unroll
        for (int nt = 0; nt < 4; nt++) {
            int n = warpN * 32 + nt * 8 + (lane & 3) * 2;
            float2 o0, o1;
            o0.x = fmaxf(cacc[mt][nt][0] * inv0 + bias0, 0.f);
            o0.y = fmaxf(cacc[mt][nt][1] * inv0 + bias0, 0.f);
            o1.x = fmaxf(cacc[mt][nt][2] * inv1 + bias1, 0.f);
            o1.y = fmaxf(cacc[mt][nt][3] * inv1 + bias1, 0.f);
            *reinterpret_cast<float2*>(op0 + n) = o0;
            *reinterpret_cast<float2*>(op1 + n) = o1;
        }
    }
}

// ---------------------------------------------------------------------------
// Kernel 2: weighted correlation (REVERTED to measured R5/R6 version)
// ---------------------------------------------------------------------------
__global__ void __launch_bounds__(224) corr_kernel(const float* __restrict__ fw)
{
    const int h0 = blockIdx.x * 4;
    const int tt = blockIdx.y;
    const int b  = blockIdx.z >> 2;
    const int g  = blockIdx.z & 3;

    __shared__ float sbuf[11008];
    float (*x1s)[4][56]  = reinterpret_cast<float (*)[4][56]>(sbuf);
    float (*x2s)[10][62] = reinterpret_cast<float (*)[10][62]>(sbuf + 1792);
    float (*ws)[49]      = reinterpret_cast<float (*)[49]>(sbuf + 6752);
    uint32_t* stage      = reinterpret_cast<uint32_t*>(sbuf);

    const int tid = threadIdx.x;
    const int py = tid / 56;
    const int px = tid % 56;

    float acc[49];
    #pragma unroll
    for (int i = 0; i < 49; i++) acc[i] = 0.f;

    const int t1 = (tt == 0) ? 0 : tt - 1;
    const float* x1base = g_xenc + (size_t)b * CE * THW + (size_t)t1 * HW;
    const float* x2base = g_xenc + (size_t)b * CE * THW + (size_t)tt * HW;

    for (int chunk = 0; chunk < 2; chunk++) {
        const int ce0 = g * 16 + chunk * 8;

        for (int i = tid; i < 8 * 49; i += 224) {
            int ce = i / 49, tap = i % 49;
            ws[ce][tap] = fw[((size_t)(ce0 + ce) * Tt + tt) * 49 + tap];
        }
        #pragma unroll
        for (int ce = 0; ce < 8; ce++) {
            x1s[ce][py][px] =
                x1base[(size_t)(ce0 + ce) * THW + (h0 + py) * Ww + px];
        }
        for (int i = tid; i < 8 * 620; i += 224) {
            int ce = i / 620, p = i % 620;
            int r = p / 62, c = p % 62;
            int hy = h0 + r - 3, wx = c - 3;
            float v = 0.f;
            if (hy >= 0 && hy < Hh && wx >= 0 && wx < Ww)
                v = x2base[(size_t)(ce0 + ce) * THW + hy * Ww + wx];
            x2s[ce][r][c] = v;
        }
        __syncthreads();

        for (int ce = 0; ce < 8; ce++) {
            float x1v = x1s[ce][py][px];
            #pragma unroll
            for (int ky = 0; ky < 7; ky++) {
                #pragma unroll
                for (int kx = 0; kx < 7; kx++) {
                    acc[ky * 7 + kx] +=
                        ws[ce][ky * 7 + kx] * x1v * x2s[ce][py + ky][px + kx];
                }
            }
        }
        __syncthreads();
    }

    #pragma unroll
    for (int tap = 0; tap < 49; tap++)
        stage[tid * 49 + tap] = tf32rna(acc[tap] * (1.f / 16.f));
    __syncthreads();

    const int wid = tid >> 5, lid = tid & 31;
    const size_t pixbase = (size_t)b * THW + (size_t)tt * HW + (size_t)h0 * Ww;
    for (int i = 0; i < 32; i++) {
        int r = wid * 32 + i;
        size_t pixel = pixbase + r;
        uint32_t* orow = g_xcorrt + pixel * KPAD + g * 49;
        orow[lid] = stage[r * 49 + lid];
        if (lid < 17) orow[32 + lid] = stage[r * 49 + 32 + lid];
        if (g == 0 && lid < 28)
            g_xcorrt[pixel * KPAD + 196 + lid] = 0u;
    }
}

// ---------------------------------------------------------------------------
// Kernel 3: dec GEMM — R5 shape (BM=128, BN=128, 256 thr, 8 warps 2m x 4n,
// warp tile 64x32, 2 CTAs/SM) upgraded to a 3-stage cp.async pipeline.
// ---------------------------------------------------------------------------
#define D_SMEM (3 * 32768)     // 96 KB: per stage A 16KB + B 16KB
#define D_AST(s) ((s) * 32768)
#define D_BST(s) ((s) * 32768 + 16384)

__global__ void __launch_bounds__(256, 2) dec_kernel(
    const float* __restrict__ x,
    const float* __restrict__ dg, const float* __restrict__ db,
    const float* __restrict__ dm, const float* __restrict__ dv,
    float* __restrict__ out)
{
    extern __shared__ char dsm[];
    const int t    = threadIdx.x;
    const int wid  = t >> 5, lane = t & 31;
    const int warpM = wid >> 2;          // 0..1
    const int warpN = wid & 3;           // 0..3

    const int nx = blockIdx.x;           // 392 n-tiles of 128
    const int m0 = blockIdx.y * 128;     // 0 or 128
    const int b  = blockIdx.z;

    const uint32_t* arow = g_dwt + (size_t)m0 * KPAD;
    const uint32_t* brow = g_xcorrt + ((size_t)b * THW + (size_t)nx * 128) * KPAD;

    float cacc[4][4][4];
    #pragma unroll
    for (int i = 0; i < 4; i++)
        #pragma unroll
        for (int j = 0; j < 4; j++)
            #pragma unroll
            for (int r = 0; r < 4; r++) cacc[i][j][r] = 0.f;

    auto load_chunk = [&](int kc, int s) {
        #pragma unroll
        for (int i = 0; i < 4; i++) {
            int e = t + 256 * i;         // 0..1023
            int row = e >> 3, c = e & 7;
            uint32_t soff = row * 128 + (((c ^ row) & 7) << 4);
            cp_async16(smem_u32(dsm + D_AST(s) + soff),
                       arow + (size_t)row * KPAD + kc * 32 + c * 4, 16);
            cp_async16(smem_u32(dsm + D_BST(s) + soff),
                       brow + (size_t)row * KPAD + kc * 32 + c * 4, 16);
        }
    };

    load_chunk(0, 0); cp_commit();
    load_chunk(1, 1); cp_commit();

    for (int c = 0; c < 7; c++) {
        const int s = c % 3;
        if (c > 0) __syncthreads();
        if (c + 2 < 7) { load_chunk(c + 2, (c + 2) % 3); cp_commit(); }
        if (c < 5) cp_wait2(); else if (c == 5) cp_wait1(); else cp_wait0();
        __syncthreads();

        const uint32_t* Ab = reinterpret_cast<const uint32_t*>(dsm + D_AST(s));
        const uint32_t* Bb = reinterpret_cast<const uint32_t*>(dsm + D_BST(s));

        #pragma unroll
        for (int ks = 0; ks < 4; ks++) {
            const int kf = ks * 8 + (lane & 3);
            uint32_t bfr[4][2];
            #pragma unroll
            for (int nt = 0; nt < 4; nt++) {
                int n = warpN * 32 + nt * 8 + (lane >> 2);
                bfr[nt][0] = Bb[swoff(n, kf)];
                bfr[nt][1] = Bb[swoff(n, kf + 4)];
            }
            #pragma unroll
            for (int mt = 0; mt < 4; mt++) {
                int r = warpM * 64 + mt * 16 + (lane >> 2);
                uint32_t afr[4];
                afr[0] = Ab[swoff(r,     kf)];
                afr[1] = Ab[swoff(r + 8, kf)];
                afr[2] = Ab[swoff(r,     kf + 4)];
                afr[3] = Ab[swoff(r + 8, kf + 4)];
                #pragma unroll
                for (int nt = 0; nt < 4; nt++)
                    mma_tf32(cacc[mt][nt], afr, bfr[nt]);
            }
        }
    }

    const size_t nbase = (size_t)nx * 128;
    #pragma unroll
    for (int mt = 0; mt < 4; mt++) {
        int mrow = m0 + warpM * 64 + mt * 16 + (lane >> 2);
        float inv0  = dg[mrow] * rsqrtf(dv[mrow] + EPSI);
        float bias0 = db[mrow] - dm[mrow] * inv0;
        float inv1  = dg[mrow + 8] * rsqrtf(dv[mrow + 8] + EPSI);
        float bias1 = db[mrow + 8] - dm[mrow + 8] * inv1;
        const float* xr0 = x   + ((size_t)b * Cc + mrow)     * THW + nbase;
        const float* xr1 = x   + ((size_t)b * Cc + mrow + 8) * THW + nbase;
        float*       op0 = out + ((size_t)b * Cc + mrow)     * THW + nbase;
        float*       op1 = out + ((size_t)b * Cc + mrow + 8) * THW + nbase;
        #pragma unroll
        for (int nt = 0; nt < 4; nt++) {
            int n = warpN * 32 + nt * 8 + (lane & 3) * 2;
            float2 r0 = *reinterpret_cast<const float2*>(xr0 + n);
            float2 r1 = *reinterpret_cast<const float2*>(xr1 + n);
            float2 o0, o1;
            o0.x = fmaxf(cacc[mt][nt][0] * inv0 + bias0 + r0.x, 0.f);
            o0.y = fmaxf(cacc[mt][nt][1] * inv0 + bias0 + r0.y, 0.f);
            o1.x = fmaxf(cacc[mt][nt][2] * inv1 + bias1 + r1.x, 0.f);
            o1.y = fmaxf(cacc[mt][nt][3] * inv1 + bias1 + r1.y, 0.f);
            *reinterpret_cast<float2*>(op0 + n) = o0;
            *reinterpret_cast<float2*>(op1 + n) = o1;
        }
    }
}

// ---------------------------------------------------------------------------
extern "C" void kernel_launch(void* const* d_in, const int* in_sizes, int n_in,
                              void* d_out, int out_size)
{
    const float* x     = (const float*)d_in[0];
    const float* enc_w = (const float*)d_in[1];
    const float* eg    = (const float*)d_in[2];
    const float* eb    = (const float*)d_in[3];
    const float* em    = (const float*)d_in[4];
    const float* ev    = (const float*)d_in[5];
    const float* fw    = (const float*)d_in[6];
    const float* dw    = (const float*)d_in[7];
    const float* dg    = (const float*)d_in[8];
    const float* db    = (const float*)d_in[9];
    const float* dm    = (const float*)d_in[10];
    const float* dv    = (const float*)d_in[11];
    float* out = (float*)d_out;

    cudaFuncSetAttribute(enc_kernel,
                         cudaFuncAttributeMaxDynamicSharedMemorySize, E_SMEM);
    cudaFuncSetAttribute(dec_kernel,
                         cudaFuncAttributeMaxDynamicSharedMemorySize, D_SMEM);

    int prep_n = Cc * KPAD + CE * Cc;
    prep_kernel<<<(prep_n + 255) / 256, 256>>>(dw, enc_w);

    dim3 g1(THW / 256, Bsz);
    enc_kernel<<<g1, 256, E_SMEM>>>(x, eg, eb, em, ev);

    dim3 g2(Hh / 4, Tt, Bsz * Gg);
    corr_kernel<<<g2, 224>>>(fw);

    dim3 g3(THW / 128, 2, Bsz);
    dec_kernel<<<g3, 256, D_SMEM>>>(x, dg, db, dm, dv, out);
}

// round 9
// speedup vs baseline: 1.5473x; 1.0448x over previous
#include <cuda_runtime.h>
#include <cstdint>

#define Bsz   4
#define Cc    256
#define CE    64
#define Tt    16
#define Hh    56
#define Ww    56
#define HW    3136
#define THW   50176
#define Gg    4
#define K2G   196
#define KPAD  224
#define EPSI  1e-5f

// Scratch (device globals: allocation-free rule)
__device__ float    g_xenc[(size_t)Bsz * CE * THW];
__device__ uint32_t g_xcorrt[(size_t)Bsz * THW * KPAD];   // [pixel][k'] tf32 bits
__device__ uint32_t g_dwt[Cc * KPAD];                     // dec_w permuted+rounded
__device__ uint32_t g_wt[CE * Cc];                        // enc_w rounded

__device__ __forceinline__ void cp_async16(uint32_t smem_addr, const void* gptr, int src_bytes) {
    asm volatile("cp.async.cg.shared.global [%0], [%1], 16, %2;"
                 :: "r"(smem_addr), "l"(gptr), "r"(src_bytes));
}
__device__ __forceinline__ void cp_commit() { asm volatile("cp.async.commit_group;"); }
__device__ __forceinline__ void cp_wait0()  { asm volatile("cp.async.wait_group 0;"); }
__device__ __forceinline__ void cp_wait1()  { asm volatile("cp.async.wait_group 1;"); }
__device__ __forceinline__ void cp_wait2()  { asm volatile("cp.async.wait_group 2;"); }

__device__ __forceinline__ uint32_t tf32rna(float f) {
    uint32_t r; asm("cvt.rna.tf32.f32 %0, %1;" : "=r"(r) : "f"(f)); return r;
}
__device__ __forceinline__ uint32_t smem_u32(const void* p) {
    return (uint32_t)__cvta_generic_to_shared(p);
}
__device__ __forceinline__ void mma_tf32(float* c, const uint32_t* a, const uint32_t* b) {
    asm volatile(
        "mma.sync.aligned.m16n8k8.row.col.f32.tf32.tf32.f32 "
        "{%0,%1,%2,%3}, {%4,%5,%6,%7}, {%8,%9}, {%0,%1,%2,%3};"
        : "+f"(c[0]), "+f"(c[1]), "+f"(c[2]), "+f"(c[3])
        : "r"(a[0]), "r"(a[1]), "r"(a[2]), "r"(a[3]), "r"(b[0]), "r"(b[1]));
}
__device__ __forceinline__ int swoff(int r, int k) {
    return r * 32 + ((((k >> 2) ^ r) & 7) << 2) + (k & 3);
}

// ---------------------------------------------------------------------------
// Kernel 0: prep
// ---------------------------------------------------------------------------
__global__ void prep_kernel(const float* __restrict__ dw, const float* __restrict__ ew)
{
    int idx = blockIdx.x * 256 + threadIdx.x;
    if (idx < Cc * KPAD) {
        int m = idx / KPAD, kp = idx % KPAD;
        uint32_t v = 0;
        if (kp < K2G) {
            int g = kp / 49, tap = kp % 49;
            v = tf32rna(dw[m * K2G + tap * 4 + g]);
        }
        g_dwt[idx] = v;
    } else if (idx < Cc * KPAD + CE * Cc) {
        int j = idx - Cc * KPAD;
        g_wt[j] = tf32rna(ew[j]);
    }
}

// ---------------------------------------------------------------------------
// Kernel 1: enc 1x1 conv on mma.sync tf32 (unchanged, measured ~75us)
// ---------------------------------------------------------------------------
#define E_SMEM (2 * (8192 + 32768))
#define E_AST(s) ((s) * 8192)
#define E_BST(s) (16384 + (s) * 32768)

__global__ void __launch_bounds__(256, 2) enc_kernel(
    const float* __restrict__ x,
    const float* __restrict__ eg, const float* __restrict__ eb,
    const float* __restrict__ em, const float* __restrict__ ev)
{
    extern __shared__ char esm[];
    const int t = threadIdx.x;
    const int wid = t >> 5, lane = t & 31;
    const int warpN = wid;
    const int n0 = blockIdx.x * 256;
    const int b  = blockIdx.y;

    const float* xb = x + (size_t)b * Cc * THW;

    float cacc[4][4][4];
    #pragma unroll
    for (int i = 0; i < 4; i++)
        #pragma unroll
        for (int j = 0; j < 4; j++)
            #pragma unroll
            for (int r = 0; r < 4; r++) cacc[i][j][r] = 0.f;

    int bpos[4];
    #pragma unroll
    for (int nt = 0; nt < 4; nt++) {
        int n = warpN * 32 + nt * 8 + (lane >> 2);
        bpos[nt] = (((n >> 2) ^ (2 * (lane & 3))) << 2) + (n & 3);
    }

    auto load_chunk = [&](int kc, int s) {
        {
            int e = t, r = e >> 3, c = e & 7;
            cp_async16(smem_u32(esm + E_AST(s) + r * 128 + (((c ^ r) & 7) << 4)),
                       g_wt + r * Cc + kc * 32 + c * 4, 16);
            e = t + 256; r = e >> 3; c = e & 7;
            cp_async16(smem_u32(esm + E_AST(s) + r * 128 + (((c ^ r) & 7) << 4)),
                       g_wt + r * Cc + kc * 32 + c * 4, 16);
        }
        #pragma unroll
        for (int i = 0; i < 8; i++) {
            int e = t + 256 * i;
            int k = e >> 6, j = e & 63;
            uint32_t dst = smem_u32(esm + E_BST(s) + k * 1024
                                    + ((j ^ (2 * (k & 3))) << 4));
            cp_async16(dst, xb + (size_t)(kc * 32 + k) * THW + n0 + j * 4, 16);
        }
    };

    load_chunk(0, 0);
    cp_commit();

    for (int c = 0; c < 8; c++) {
        const int s = c & 1;
        if (c > 0) __syncthreads();
        if (c + 1 < 8) { load_chunk(c + 1, s ^ 1); cp_commit(); cp_wait1(); }
        else cp_wait0();
        __syncthreads();

        const uint32_t* Ab = reinterpret_cast<const uint32_t*>(esm + E_AST(s));
        const uint32_t* Bb = reinterpret_cast<const uint32_t*>(esm + E_BST(s));

        #pragma unroll
        for (int ks = 0; ks < 4; ks++) {
            const int kf = ks * 8 + (lane & 3);
            uint32_t bfr[4][2];
            #pragma unroll
            for (int nt = 0; nt < 4; nt++) {
                bfr[nt][0] = tf32rna(__uint_as_float(Bb[kf * 256 + bpos[nt]]));
                bfr[nt][1] = tf32rna(__uint_as_float(Bb[(kf + 4) * 256 + bpos[nt]]));
            }
            #pragma unroll
            for (int mt = 0; mt < 4; mt++) {
                int r = mt * 16 + (lane >> 2);
                uint32_t afr[4];
                afr[0] = Ab[swoff(r,     kf)];
                afr[1] = Ab[swoff(r + 8, kf)];
                afr[2] = Ab[swoff(r,     kf + 4)];
                afr[3] = Ab[swoff(r + 8, kf + 4)];
                #pragma unroll
                for (int nt = 0; nt < 4; nt++)
                    mma_tf32(cacc[mt][nt], afr, bfr[nt]);
            }
        }
    }

    #pragma unroll
    for (int mt = 0; mt < 4; mt++) {
        int ce0 = mt * 16 + (lane >> 2);
        float inv0  = eg[ce0] * rsqrtf(ev[ce0] + EPSI);
        float bias0 = eb[ce0] - em[ce0] * inv0;
        float inv1  = eg[ce0 + 8] * rsqrtf(ev[ce0 + 8] + EPSI);
        float bias1 = eb[ce0 + 8] - em[ce0 + 8] * inv1;
        float* op0 = g_xenc + ((size_t)b * CE + ce0)     * THW + n0;
        float* op1 = g_xenc + ((size_t)b * CE + ce0 + 8) * THW + n0;
        #pragma unroll
        for (int nt = 0; nt < 4; nt++) {
            int n = warpN * 32 + nt * 8 + (lane & 3) * 2;
            float2 o0, o1;
            o0.x = fmaxf(cacc[mt][nt][0] * inv0 + bias0, 0.f);
            o0.y = fmaxf(cacc[mt][nt][1] * inv0 + bias0, 0.f);
            o1.x = fmaxf(cacc[mt][nt][2] * inv1 + bias1, 0.f);
            o1.y = fmaxf(cacc[mt][nt][3] * inv1 + bias1, 0.f);
            *reinterpret_cast<float2*>(op0 + n) = o0;
            *reinterpret_cast<float2*>(op1 + n) = o1;
        }
    }
}

// ---------------------------------------------------------------------------
// Kernel 2: corr v3 — 224 thr, 8-row tile, 2 px/thread, all 16 ch resident,
// ky-outer acc[7][2], full x2 tile (no ring), vectorized LDS, 2 CTAs/SM.
// smem floats: x1[16][8][56] @0, x2[16][14][64] @7168, w[16][7][8] @21504,
//              stage[3136] @22400  -> 25536 f = 102144 B
// ---------------------------------------------------------------------------
#define C_SMEM (25536 * 4)
#define CX1(ce, r, px)    ((ce) * 448 + (r) * 56 + (px))
#define CX2(ce, row, col) (7168 + (ce) * 896 + (row) * 64 + (col))
#define CW(ce, ky, k)     (21504 + (ce) * 56 + (ky) * 8 + (k))
#define CST(j)            (22400 + (j))

__global__ void __launch_bounds__(224, 2) corr_kernel(const float* __restrict__ fw)
{
    extern __shared__ float cs[];
    const int tid = threadIdx.x;
    const int r   = tid / 28;      // 0..7
    const int q   = tid % 28;
    const int px0 = q * 2;         // 0..54

    const int h0 = blockIdx.x * 8;
    const int tt = blockIdx.y;
    const int b  = blockIdx.z >> 2;
    const int g  = blockIdx.z & 3;
    const int ce0 = g * 16;

    const int t1 = (tt == 0) ? 0 : tt - 1;
    const float* x1base = g_xenc + (size_t)b * CE * THW + (size_t)t1 * HW;
    const float* x2base = g_xenc + (size_t)b * CE * THW + (size_t)tt * HW;
    const size_t pixbase = (size_t)b * THW + (size_t)tt * HW + (size_t)h0 * Ww;

    // weights: [ce][ky][k] with row pad 8
    for (int i = tid; i < 16 * 49; i += 224) {
        int ce = i / 49, tap = i % 49;
        cs[CW(ce, tap / 7, tap % 7)] = fw[((size_t)(ce0 + ce) * Tt + tt) * 49 + tap];
    }
    // x1: 16 x 8 x 56
    for (int i = tid; i < 16 * 448; i += 224) {
        int ce = i / 448, rem = i % 448;
        int rr = rem / 56, px = rem % 56;
        cs[CX1(ce, rr, px)] = x1base[(size_t)(ce0 + ce) * THW + (h0 + rr) * Ww + px];
    }
    // x2 halo tile: 16 x 14 x 64, zero-padded
    for (int i = tid; i < 16 * 896; i += 224) {
        int ce = i / 896, rem = i % 896;
        int row = rem / 64, col = rem % 64;
        int hy = h0 + row - 3, wx = col - 3;
        float v = 0.f;
        if (hy >= 0 && hy < Hh && wx >= 0 && wx < Ww)
            v = x2base[(size_t)(ce0 + ce) * THW + hy * Ww + wx];
        cs[CX2(ce, row, col)] = v;
    }
    // zero-pad k' 196..223 (once per pixel; g==0 blocks own it)
    if (g == 0) {
        for (int i = tid; i < 448 * 28; i += 224) {
            int pl = i / 28, j = i % 28;
            g_xcorrt[(pixbase + pl) * KPAD + 196 + j] = 0u;
        }
    }
    __syncthreads();

    #pragma unroll 1
    for (int ky = 0; ky < 7; ky++) {
        float acc[7][2];
        #pragma unroll
        for (int kx = 0; kx < 7; kx++) { acc[kx][0] = 0.f; acc[kx][1] = 0.f; }

        const int zr = r + ky;     // x2 tile row (0..13)

        #pragma unroll 4
        for (int ce = 0; ce < 16; ce++) {
            float2 y2 = *reinterpret_cast<const float2*>(&cs[CX1(ce, r, px0)]);
            const float* zp = &cs[CX2(ce, zr, px0)];
            float z[8];
            *reinterpret_cast<float2*>(&z[0]) = *reinterpret_cast<const float2*>(zp);
            *reinterpret_cast<float2*>(&z[2]) = *reinterpret_cast<const float2*>(zp + 2);
            *reinterpret_cast<float2*>(&z[4]) = *reinterpret_cast<const float2*>(zp + 4);
            *reinterpret_cast<float2*>(&z[6]) = *reinterpret_cast<const float2*>(zp + 6);
            const float* wp = &cs[CW(ce, ky, 0)];
            float4 w4 = *reinterpret_cast<const float4*>(wp);
            float2 w2 = *reinterpret_cast<const float2*>(wp + 4);
            float  w6 = wp[6];
            float w[7] = {w4.x, w4.y, w4.z, w4.w, w2.x, w2.y, w6};
            #pragma unroll
            for (int kx = 0; kx < 7; kx++) {
                acc[kx][0] += w[kx] * (y2.x * z[kx]);
                acc[kx][1] += w[kx] * (y2.y * z[kx + 1]);
            }
        }

        // stage (tf32-rounded bits)
        #pragma unroll
        for (int p = 0; p < 2; p++)
            #pragma unroll
            for (int kx = 0; kx < 7; kx++)
                cs[CST((r * 56 + px0 + p) * 7 + kx)] =
                    __uint_as_float(tf32rna(acc[kx][p] * (1.f / 16.f)));
        __syncthreads();

        // store: per pixel 7 consecutive k' at g*49 + ky*7
        {
            uint32_t* gb = g_xcorrt + (size_t)g * 49 + (size_t)ky * 7;
            for (int i = tid; i < 3136; i += 224) {
                int pl = i / 7, kx = i % 7;
                gb[(pixbase + pl) * KPAD + kx] = __float_as_uint(cs[CST(i)]);
            }
        }
        __syncthreads();
    }
}

// ---------------------------------------------------------------------------
// Kernel 3: dec GEMM — identical to measured-best R8 except grid interleave:
// m-tile pairs adjacent in grid.x so B hits L2 on the second m-tile.
// ---------------------------------------------------------------------------
#define D_SMEM (3 * 32768)
#define D_AST(s) ((s) * 32768)
#define D_BST(s) ((s) * 32768 + 16384)

__global__ void __launch_bounds__(256, 2) dec_kernel(
    const float* __restrict__ x,
    const float* __restrict__ dg, const float* __restrict__ db,
    const float* __restrict__ dm, const float* __restrict__ dv,
    float* __restrict__ out)
{
    extern __shared__ char dsm[];
    const int t    = threadIdx.x;
    const int wid  = t >> 5, lane = t & 31;
    const int warpM = wid >> 2;
    const int warpN = wid & 3;

    const int nx = blockIdx.x >> 1;          // 392 n-tiles of 128
    const int m0 = (blockIdx.x & 1) * 128;   // m-tile pairs adjacent
    const int b  = blockIdx.y;

    const uint32_t* arow = g_dwt + (size_t)m0 * KPAD;
    const uint32_t* brow = g_xcorrt + ((size_t)b * THW + (size_t)nx * 128) * KPAD;

    float cacc[4][4][4];
    #pragma unroll
    for (int i = 0; i < 4; i++)
        #pragma unroll
        for (int j = 0; j < 4; j++)
            #pragma unroll
            for (int r = 0; r < 4; r++) cacc[i][j][r] = 0.f;

    auto load_chunk = [&](int kc, int s) {
        #pragma unroll
        for (int i = 0; i < 4; i++) {
            int e = t + 256 * i;
            int row = e >> 3, c = e & 7;
            uint32_t soff = row * 128 + (((c ^ row) & 7) << 4);
            cp_async16(smem_u32(dsm + D_AST(s) + soff),
                       arow + (size_t)row * KPAD + kc * 32 + c * 4, 16);
            cp_async16(smem_u32(dsm + D_BST(s) + soff),
                       brow + (size_t)row * KPAD + kc * 32 + c * 4, 16);
        }
    };

    load_chunk(0, 0); cp_commit();
    load_chunk(1, 1); cp_commit();

    for (int c = 0; c < 7; c++) {
        const int s = c % 3;
        if (c > 0) __syncthreads();
        if (c + 2 < 7) { load_chunk(c + 2, (c + 2) % 3); cp_commit(); }
        if (c < 5) cp_wait2(); else if (c == 5) cp_wait1(); else cp_wait0();
        __syncthreads();

        const uint32_t* Ab = reinterpret_cast<const uint32_t*>(dsm + D_AST(s));
        const uint32_t* Bb = reinterpret_cast<const uint32_t*>(dsm + D_BST(s));

        #pragma unroll
        for (int ks = 0; ks < 4; ks++) {
            const int kf = ks * 8 + (lane & 3);
            uint32_t bfr[4][2];
            #pragma unroll
            for (int nt = 0; nt < 4; nt++) {
                int n = warpN * 32 + nt * 8 + (lane >> 2);
                bfr[nt][0] = Bb[swoff(n, kf)];
                bfr[nt][1] = Bb[swoff(n, kf + 4)];
            }
            #pragma unroll
            for (int mt = 0; mt < 4; mt++) {
                int r = warpM * 64 + mt * 16 + (lane >> 2);
                uint32_t afr[4];
                afr[0] = Ab[swoff(r,     kf)];
                afr[1] = Ab[swoff(r + 8, kf)];
                afr[2] = Ab[swoff(r,     kf + 4)];
                afr[3] = Ab[swoff(r + 8, kf + 4)];
                #pragma unroll
                for (int nt = 0; nt < 4; nt++)
                    mma_tf32(cacc[mt][nt], afr, bfr[nt]);
            }
        }
    }

    const size_t nbase = (size_t)nx * 128;
    #pragma unroll
    for (int mt = 0; mt < 4; mt++) {
        int mrow = m0 + warpM * 64 + mt * 16 + (lane >> 2);
        float inv0  = dg[mrow] * rsqrtf(dv[mrow] + EPSI);
        float bias0 = db[mrow] - dm[mrow] * inv0;
        float inv1  = dg[mrow + 8] * rsqrtf(dv[mrow + 8] + EPSI);
        float bias1 = db[mrow + 8] - dm[mrow + 8] * inv1;
        const float* xr0 = x   + ((size_t)b * Cc + mrow)     * THW + nbase;
        const float* xr1 = x   + ((size_t)b * Cc + mrow + 8) * THW + nbase;
        float*       op0 = out + ((size_t)b * Cc + mrow)     * THW + nbase;
        float*       op1 = out + ((size_t)b * Cc + mrow + 8) * THW + nbase;
        #pragma unroll
        for (int nt = 0; nt < 4; nt++) {
            int n = warpN * 32 + nt * 8 + (lane & 3) * 2;
            float2 r0 = *reinterpret_cast<const float2*>(xr0 + n);
            float2 r1 = *reinterpret_cast<const float2*>(xr1 + n);
            float2 o0, o1;
            o0.x = fmaxf(cacc[mt][nt][0] * inv0 + bias0 + r0.x, 0.f);
            o0.y = fmaxf(cacc[mt][nt][1] * inv0 + bias0 + r0.y, 0.f);
            o1.x = fmaxf(cacc[mt][nt][2] * inv1 + bias1 + r1.x, 0.f);
            o1.y = fmaxf(cacc[mt][nt][3] * inv1 + bias1 + r1.y, 0.f);
            *reinterpret_cast<float2*>(op0 + n) = o0;
            *reinterpret_cast<float2*>(op1 + n) = o1;
        }
    }
}

// ---------------------------------------------------------------------------
extern "C" void kernel_launch(void* const* d_in, const int* in_sizes, int n_in,
                              void* d_out, int out_size)
{
    const float* x     = (const float*)d_in[0];
    const float* enc_w = (const float*)d_in[1];
    const float* eg    = (const float*)d_in[2];
    const float* eb    = (const float*)d_in[3];
    const float* em    = (const float*)d_in[4];
    const float* ev    = (const float*)d_in[5];
    const float* fw    = (const float*)d_in[6];
    const float* dw    = (const float*)d_in[7];
    const float* dg    = (const float*)d_in[8];
    const float* db    = (const float*)d_in[9];
    const float* dm    = (const float*)d_in[10];
    const float* dv    = (const float*)d_in[11];
    float* out = (float*)d_out;

    cudaFuncSetAttribute(enc_kernel,
                         cudaFuncAttributeMaxDynamicSharedMemorySize, E_SMEM);
    cudaFuncSetAttribute(corr_kernel,
                         cudaFuncAttributeMaxDynamicSharedMemorySize, C_SMEM);
    cudaFuncSetAttribute(dec_kernel,
                         cudaFuncAttributeMaxDynamicSharedMemorySize, D_SMEM);

    int prep_n = Cc * KPAD + CE * Cc;
    prep_kernel<<<(prep_n + 255) / 256, 256>>>(dw, enc_w);

    dim3 g1(THW / 256, Bsz);
    enc_kernel<<<g1, 256, E_SMEM>>>(x, eg, eb, em, ev);

    dim3 g2(Hh / 8, Tt, Bsz * Gg);
    corr_kernel<<<g2, 224, C_SMEM>>>(fw);

    dim3 g3(THW / 128 * 2, Bsz);
    dec_kernel<<<g3, 256, D_SMEM>>>(x, dg, db, dm, dv, out);
}

// round 10
// speedup vs baseline: 1.7398x; 1.1244x over previous
#include <cuda_runtime.h>
#include <cuda_bf16.h>
#include <cstdint>

#define Bsz   4
#define Cc    256
#define CE    64
#define Tt    16
#define Hh    56
#define Ww    56
#define HW    3136
#define THW   50176
#define Gg    4
#define K2G   196
#define KPAD  224            // 28 islands of 8 (g*56 + ky*8 + kx, kx<7 valid)
#define EPSI  1e-5f

// Scratch (device globals: allocation-free rule)
__device__ float    g_xenc[(size_t)Bsz * CE * THW];
__device__ uint16_t g_xcorrb[(size_t)Bsz * THW * KPAD];   // [pixel][k''] bf16
__device__ uint16_t g_dwb[Cc * KPAD];                     // dec_w permuted bf16
__device__ uint32_t g_wt[CE * Cc];                        // enc_w tf32 bits

__device__ __forceinline__ void cp_async16(uint32_t smem_addr, const void* gptr, int src_bytes) {
    asm volatile("cp.async.cg.shared.global [%0], [%1], 16, %2;"
                 :: "r"(smem_addr), "l"(gptr), "r"(src_bytes));
}
__device__ __forceinline__ void cp_commit() { asm volatile("cp.async.commit_group;"); }
__device__ __forceinline__ void cp_wait0()  { asm volatile("cp.async.wait_group 0;"); }
__device__ __forceinline__ void cp_wait1()  { asm volatile("cp.async.wait_group 1;"); }
__device__ __forceinline__ void cp_wait2()  { asm volatile("cp.async.wait_group 2;"); }

__device__ __forceinline__ uint32_t tf32rna(float f) {
    uint32_t r; asm("cvt.rna.tf32.f32 %0, %1;" : "=r"(r) : "f"(f)); return r;
}
__device__ __forceinline__ uint32_t bf2(float lo, float hi) {
    uint32_t r; asm("cvt.rn.bf16x2.f32 %0, %1, %2;" : "=r"(r) : "f"(hi), "f"(lo));
    return r;
}
__device__ __forceinline__ uint32_t smem_u32(const void* p) {
    return (uint32_t)__cvta_generic_to_shared(p);
}
__device__ __forceinline__ void mma_tf32(float* c, const uint32_t* a, const uint32_t* b) {
    asm volatile(
        "mma.sync.aligned.m16n8k8.row.col.f32.tf32.tf32.f32 "
        "{%0,%1,%2,%3}, {%4,%5,%6,%7}, {%8,%9}, {%0,%1,%2,%3};"
        : "+f"(c[0]), "+f"(c[1]), "+f"(c[2]), "+f"(c[3])
        : "r"(a[0]), "r"(a[1]), "r"(a[2]), "r"(a[3]), "r"(b[0]), "r"(b[1]));
}
__device__ __forceinline__ void mma_bf16(float* c, const uint32_t* a, const uint32_t* b) {
    asm volatile(
        "mma.sync.aligned.m16n8k16.row.col.f32.bf16.bf16.f32 "
        "{%0,%1,%2,%3}, {%4,%5,%6,%7}, {%8,%9}, {%0,%1,%2,%3};"
        : "+f"(c[0]), "+f"(c[1]), "+f"(c[2]), "+f"(c[3])
        : "r"(a[0]), "r"(a[1]), "r"(a[2]), "r"(a[3]), "r"(b[0]), "r"(b[1]));
}
// tf32 f32-tile swizzle (enc)
__device__ __forceinline__ int swoff(int r, int k) {
    return r * 32 + ((((k >> 2) ^ r) & 7) << 2) + (k & 3);
}
// bf16 tile: rows of 16 u32 words; 4-word XOR swizzle
__device__ __forceinline__ int dwoff(int r, int w) {
    return r * 16 + ((w) ^ ((((r) >> 1) & 3) << 2));
}

// ---------------------------------------------------------------------------
// Kernel 0: prep — dec_w -> bf16 islands; enc_w -> tf32 bits
// ---------------------------------------------------------------------------
__global__ void prep_kernel(const float* __restrict__ dw, const float* __restrict__ ew)
{
    int idx = blockIdx.x * 256 + threadIdx.x;
    if (idx < Cc * KPAD) {
        int m = idx / KPAD, kp = idx % KPAD;
        int g = kp / 56, rem = kp % 56;
        int ky = rem / 8, kx = rem % 8;
        float v = 0.f;
        if (kx < 7) v = dw[m * K2G + (ky * 7 + kx) * 4 + g];
        g_dwb[idx] = (uint16_t)(bf2(v, 0.f) & 0xFFFF);
    } else if (idx < Cc * KPAD + CE * Cc) {
        int j = idx - Cc * KPAD;
        g_wt[j] = tf32rna(ew[j]);
    }
}

// ---------------------------------------------------------------------------
// Kernel 1: enc 1x1 conv on mma.sync tf32 (unchanged, measured ~75us)
// ---------------------------------------------------------------------------
#define E_SMEM (2 * (8192 + 32768))
#define E_AST(s) ((s) * 8192)
#define E_BST(s) (16384 + (s) * 32768)

__global__ void __launch_bounds__(256, 2) enc_kernel(
    const float* __restrict__ x,
    const float* __restrict__ eg, const float* __restrict__ eb,
    const float* __restrict__ em, const float* __restrict__ ev)
{
    extern __shared__ char esm[];
    const int t = threadIdx.x;
    const int wid = t >> 5, lane = t & 31;
    const int warpN = wid;
    const int n0 = blockIdx.x * 256;
    const int b  = blockIdx.y;

    const float* xb = x + (size_t)b * Cc * THW;

    float cacc[4][4][4];
    #pragma unroll
    for (int i = 0; i < 4; i++)
        #pragma unroll
        for (int j = 0; j < 4; j++)
            #pragma unroll
            for (int r = 0; r < 4; r++) cacc[i][j][r] = 0.f;

    int bpos[4];
    #pragma unroll
    for (int nt = 0; nt < 4; nt++) {
        int n = warpN * 32 + nt * 8 + (lane >> 2);
        bpos[nt] = (((n >> 2) ^ (2 * (lane & 3))) << 2) + (n & 3);
    }

    auto load_chunk = [&](int kc, int s) {
        {
            int e = t, r = e >> 3, c = e & 7;
            cp_async16(smem_u32(esm + E_AST(s) + r * 128 + (((c ^ r) & 7) << 4)),
                       g_wt + r * Cc + kc * 32 + c * 4, 16);
            e = t + 256; r = e >> 3; c = e & 7;
            cp_async16(smem_u32(esm + E_AST(s) + r * 128 + (((c ^ r) & 7) << 4)),
                       g_wt + r * Cc + kc * 32 + c * 4, 16);
        }
        #pragma unroll
        for (int i = 0; i < 8; i++) {
            int e = t + 256 * i;
            int k = e >> 6, j = e & 63;
            uint32_t dst = smem_u32(esm + E_BST(s) + k * 1024
                                    + ((j ^ (2 * (k & 3))) << 4));
            cp_async16(dst, xb + (size_t)(kc * 32 + k) * THW + n0 + j * 4, 16);
        }
    };

    load_chunk(0, 0);
    cp_commit();

    for (int c = 0; c < 8; c++) {
        const int s = c & 1;
        if (c > 0) __syncthreads();
        if (c + 1 < 8) { load_chunk(c + 1, s ^ 1); cp_commit(); cp_wait1(); }
        else cp_wait0();
        __syncthreads();

        const uint32_t* Ab = reinterpret_cast<const uint32_t*>(esm + E_AST(s));
        const uint32_t* Bb = reinterpret_cast<const uint32_t*>(esm + E_BST(s));

        #pragma unroll
        for (int ks = 0; ks < 4; ks++) {
            const int kf = ks * 8 + (lane & 3);
            uint32_t bfr[4][2];
            #pragma unroll
            for (int nt = 0; nt < 4; nt++) {
                bfr[nt][0] = tf32rna(__uint_as_float(Bb[kf * 256 + bpos[nt]]));
                bfr[nt][1] = tf32rna(__uint_as_float(Bb[(kf + 4) * 256 + bpos[nt]]));
            }
            #pragma unroll
            for (int mt = 0; mt < 4; mt++) {
                int r = mt * 16 + (lane >> 2);
                uint32_t afr[4];
                afr[0] = Ab[swoff(r,     kf)];
                afr[1] = Ab[swoff(r + 8, kf)];
                afr[2] = Ab[swoff(r,     kf + 4)];
                afr[3] = Ab[swoff(r + 8, kf + 4)];
                #pragma unroll
                for (int nt = 0; nt < 4; nt++)
                    mma_tf32(cacc[mt][nt], afr, bfr[nt]);
            }
        }
    }

    #pragma unroll
    for (int mt = 0; mt < 4; mt++) {
        int ce0 = mt * 16 + (lane >> 2);
        float inv0  = eg[ce0] * rsqrtf(ev[ce0] + EPSI);
        float bias0 = eb[ce0] - em[ce0] * inv0;
        float inv1  = eg[ce0 + 8] * rsqrtf(ev[ce0 + 8] + EPSI);
        float bias1 = eb[ce0 + 8] - em[ce0 + 8] * inv1;
        float* op0 = g_xenc + ((size_t)b * CE + ce0)     * THW + n0;
        float* op1 = g_xenc + ((size_t)b * CE + ce0 + 8) * THW + n0;
        #pragma unroll
        for (int nt = 0; nt < 4; nt++) {
            int n = warpN * 32 + nt * 8 + (lane & 3) * 2;
            float2 o0, o1;
            o0.x = fmaxf(cacc[mt][nt][0] * inv0 + bias0, 0.f);
            o0.y = fmaxf(cacc[mt][nt][1] * inv0 + bias0, 0.f);
            o1.x = fmaxf(cacc[mt][nt][2] * inv1 + bias1, 0.f);
            o1.y = fmaxf(cacc[mt][nt][3] * inv1 + bias1, 0.f);
            *reinterpret_cast<float2*>(op0 + n) = o0;
            *reinterpret_cast<float2*>(op1 + n) = o1;
        }
    }
}

// ---------------------------------------------------------------------------
// Kernel 2: corr v3 (R9 shape) -> bf16 island stores (1 STG.128 / pixel / ky)
// ---------------------------------------------------------------------------
#define C_SMEM (25536 * 4)
#define CX1(ce, r, px)    ((ce) * 448 + (r) * 56 + (px))
#define CX2(ce, row, col) (7168 + (ce) * 896 + (row) * 64 + (col))
#define CW(ce, ky, k)     (21504 + (ce) * 56 + (ky) * 8 + (k))
#define CST(j)            (22400 + (j))

__global__ void __launch_bounds__(224, 2) corr_kernel(const float* __restrict__ fw)
{
    extern __shared__ float cs[];
    const int tid = threadIdx.x;
    const int r   = tid / 28;
    const int q   = tid % 28;
    const int px0 = q * 2;

    const int h0 = blockIdx.x * 8;
    const int tt = blockIdx.y;
    const int b  = blockIdx.z >> 2;
    const int g  = blockIdx.z & 3;
    const int ce0 = g * 16;

    const int t1 = (tt == 0) ? 0 : tt - 1;
    const float* x1base = g_xenc + (size_t)b * CE * THW + (size_t)t1 * HW;
    const float* x2base = g_xenc + (size_t)b * CE * THW + (size_t)tt * HW;
    const size_t pixbase = (size_t)b * THW + (size_t)tt * HW + (size_t)h0 * Ww;

    for (int i = tid; i < 16 * 49; i += 224) {
        int ce = i / 49, tap = i % 49;
        cs[CW(ce, tap / 7, tap % 7)] = fw[((size_t)(ce0 + ce) * Tt + tt) * 49 + tap];
    }
    for (int i = tid; i < 16 * 448; i += 224) {
        int ce = i / 448, rem = i % 448;
        int rr = rem / 56, px = rem % 56;
        cs[CX1(ce, rr, px)] = x1base[(size_t)(ce0 + ce) * THW + (h0 + rr) * Ww + px];
    }
    for (int i = tid; i < 16 * 896; i += 224) {
        int ce = i / 896, rem = i % 896;
        int row = rem / 64, col = rem % 64;
        int hy = h0 + row - 3, wx = col - 3;
        float v = 0.f;
        if (hy >= 0 && hy < Hh && wx >= 0 && wx < Ww)
            v = x2base[(size_t)(ce0 + ce) * THW + hy * Ww + wx];
        cs[CX2(ce, row, col)] = v;
    }
    __syncthreads();

    #pragma unroll 1
    for (int ky = 0; ky < 7; ky++) {
        float acc[7][2];
        #pragma unroll
        for (int kx = 0; kx < 7; kx++) { acc[kx][0] = 0.f; acc[kx][1] = 0.f; }

        const int zr = r + ky;

        #pragma unroll 4
        for (int ce = 0; ce < 16; ce++) {
            float2 y2 = *reinterpret_cast<const float2*>(&cs[CX1(ce, r, px0)]);
            const float* zp = &cs[CX2(ce, zr, px0)];
            float z[8];
            *reinterpret_cast<float2*>(&z[0]) = *reinterpret_cast<const float2*>(zp);
            *reinterpret_cast<float2*>(&z[2]) = *reinterpret_cast<const float2*>(zp + 2);
            *reinterpret_cast<float2*>(&z[4]) = *reinterpret_cast<const float2*>(zp + 4);
            *reinterpret_cast<float2*>(&z[6]) = *reinterpret_cast<const float2*>(zp + 6);
            const float* wp = &cs[CW(ce, ky, 0)];
            float4 w4 = *reinterpret_cast<const float4*>(wp);
            float2 w2 = *reinterpret_cast<const float2*>(wp + 4);
            float  w6 = wp[6];
            float w[7] = {w4.x, w4.y, w4.z, w4.w, w2.x, w2.y, w6};
            #pragma unroll
            for (int kx = 0; kx < 7; kx++) {
                acc[kx][0] += w[kx] * (y2.x * z[kx]);
                acc[kx][1] += w[kx] * (y2.y * z[kx + 1]);
            }
        }

        #pragma unroll
        for (int p = 0; p < 2; p++)
            #pragma unroll
            for (int kx = 0; kx < 7; kx++)
                cs[CST((r * 56 + px0 + p) * 7 + kx)] = acc[kx][p] * (1.f / 16.f);
        __syncthreads();

        // bf16 island store: one 16B write per pixel (g*56 + ky*8 + 0..7)
        {
            uint16_t* gb = g_xcorrb + (size_t)g * 56 + (size_t)ky * 8;
            for (int i = tid; i < 448; i += 224) {
                const float* sp = &cs[CST(i * 7)];
                uint4 v;
                v.x = bf2(sp[0], sp[1]);
                v.y = bf2(sp[2], sp[3]);
                v.z = bf2(sp[4], sp[5]);
                v.w = bf2(sp[6], 0.f);
                *reinterpret_cast<uint4*>(gb + (pixbase + i) * KPAD) = v;
            }
        }
        __syncthreads();
    }
}

// ---------------------------------------------------------------------------
// Kernel 3: dec GEMM on mma.sync.m16n8k16 bf16. BM=128, BN=128, 256 thr,
// 8 warps (2m x 4n), warp tile 64x32, 3-stage cp.async, 2 CTAs/SM,
// m-pair grid interleave. bf16 tiles (8KB each), 4-word XOR swizzle.
// ---------------------------------------------------------------------------
#define D_SMEM (3 * 16384)
#define D_AST(s) ((s) * 16384)
#define D_BST(s) ((s) * 16384 + 8192)

__global__ void __launch_bounds__(256, 2) dec_kernel(
    const float* __restrict__ x,
    const float* __restrict__ dg, const float* __restrict__ db,
    const float* __restrict__ dm, const float* __restrict__ dv,
    float* __restrict__ out)
{
    extern __shared__ char dsm[];
    const int t    = threadIdx.x;
    const int wid  = t >> 5, lane = t & 31;
    const int warpM = wid >> 2;
    const int warpN = wid & 3;

    const int nx = blockIdx.x >> 1;
    const int m0 = (blockIdx.x & 1) * 128;
    const int b  = blockIdx.y;

    const uint16_t* arow = g_dwb + (size_t)m0 * KPAD;
    const uint16_t* brow = g_xcorrb + ((size_t)b * THW + (size_t)nx * 128) * KPAD;

    float cacc[4][4][4];
    #pragma unroll
    for (int i = 0; i < 4; i++)
        #pragma unroll
        for (int j = 0; j < 4; j++)
            #pragma unroll
            for (int r = 0; r < 4; r++) cacc[i][j][r] = 0.f;

    // per chunk: A 128 rows x 4 16B-chunks, B same -> 4 cp.async per thread
    auto load_chunk = [&](int kc, int s) {
        #pragma unroll
        for (int i = 0; i < 2; i++) {
            int e = t + 256 * i;           // 0..511
            int row = e >> 2, c = e & 3;
            uint32_t soff = row * 64 + ((c ^ ((row >> 1) & 3)) << 4);
            cp_async16(smem_u32(dsm + D_AST(s) + soff),
                       arow + (size_t)row * KPAD + kc * 32 + c * 8, 16);
            cp_async16(smem_u32(dsm + D_BST(s) + soff),
                       brow + (size_t)row * KPAD + kc * 32 + c * 8, 16);
        }
    };

    load_chunk(0, 0); cp_commit();
    load_chunk(1, 1); cp_commit();

    for (int c = 0; c < 7; c++) {
        const int s = c % 3;
        if (c > 0) __syncthreads();
        if (c + 2 < 7) { load_chunk(c + 2, (c + 2) % 3); cp_commit(); }
        if (c < 5) cp_wait2(); else if (c == 5) cp_wait1(); else cp_wait0();
        __syncthreads();

        const uint32_t* Ab = reinterpret_cast<const uint32_t*>(dsm + D_AST(s));
        const uint32_t* Bb = reinterpret_cast<const uint32_t*>(dsm + D_BST(s));

        #pragma unroll
        for (int ks = 0; ks < 2; ks++) {
            const int wb = ks * 8 + (lane & 3);
            uint32_t bfr[4][2];
            #pragma unroll
            for (int nt = 0; nt < 4; nt++) {
                int n = warpN * 32 + nt * 8 + (lane >> 2);
                bfr[nt][0] = Bb[dwoff(n, wb)];
                bfr[nt][1] = Bb[dwoff(n, wb + 4)];
            }
            #pragma unroll
            for (int mt = 0; mt < 4; mt++) {
                int r = warpM * 64 + mt * 16 + (lane >> 2);
                uint32_t afr[4];
                afr[0] = Ab[dwoff(r,     wb)];
                afr[1] = Ab[dwoff(r + 8, wb)];
                afr[2] = Ab[dwoff(r,     wb + 4)];
                afr[3] = Ab[dwoff(r + 8, wb + 4)];
                #pragma unroll
                for (int nt = 0; nt < 4; nt++)
                    mma_bf16(cacc[mt][nt], afr, bfr[nt]);
            }
        }
    }

    const size_t nbase = (size_t)nx * 128;
    #pragma unroll
    for (int mt = 0; mt < 4; mt++) {
        int mrow = m0 + warpM * 64 + mt * 16 + (lane >> 2);
        float inv0  = dg[mrow] * rsqrtf(dv[mrow] + EPSI);
        float bias0 = db[mrow] - dm[mrow] * inv0;
        float inv1  = dg[mrow + 8] * rsqrtf(dv[mrow + 8] + EPSI);
        float bias1 = db[mrow + 8] - dm[mrow + 8] * inv1;
        const float* xr0 = x   + ((size_t)b * Cc + mrow)     * THW + nbase;
        const float* xr1 = x   + ((size_t)b * Cc + mrow + 8) * THW + nbase;
        float*       op0 = out + ((size_t)b * Cc + mrow)     * THW + nbase;
        float*       op1 = out + ((size_t)b * Cc + mrow + 8) * THW + nbase;
        #pragma unroll
        for (int nt = 0; nt < 4; nt++) {
            int n = warpN * 32 + nt * 8 + (lane & 3) * 2;
            float2 r0 = *reinterpret_cast<const float2*>(xr0 + n);
            float2 r1 = *reinterpret_cast<const float2*>(xr1 + n);
            float2 o0, o1;
            o0.x = fmaxf(cacc[mt][nt][0] * inv0 + bias0 + r0.x, 0.f);
            o0.y = fmaxf(cacc[mt][nt][1] * inv0 + bias0 + r0.y, 0.f);
            o1.x = fmaxf(cacc[mt][nt][2] * inv1 + bias1 + r1.x, 0.f);
            o1.y = fmaxf(cacc[mt][nt][3] * inv1 + bias1 + r1.y, 0.f);
            *reinterpret_cast<float2*>(op0 + n) = o0;
            *reinterpret_cast<float2*>(op1 + n) = o1;
        }
    }
}

// ---------------------------------------------------------------------------
extern "C" void kernel_launch(void* const* d_in, const int* in_sizes, int n_in,
                              void* d_out, int out_size)
{
    const float* x     = (const float*)d_in[0];
    const float* enc_w = (const float*)d_in[1];
    const float* eg    = (const float*)d_in[2];
    const float* eb    = (const float*)d_in[3];
    const float* em    = (const float*)d_in[4];
    const float* ev    = (const float*)d_in[5];
    const float* fw    = (const float*)d_in[6];
    const float* dw    = (const float*)d_in[7];
    const float* dg    = (const float*)d_in[8];
    const float* db    = (const float*)d_in[9];
    const float* dm    = (const float*)d_in[10];
    const float* dv    = (const float*)d_in[11];
    float* out = (float*)d_out;

    cudaFuncSetAttribute(enc_kernel,
                         cudaFuncAttributeMaxDynamicSharedMemorySize, E_SMEM);
    cudaFuncSetAttribute(corr_kernel,
                         cudaFuncAttributeMaxDynamicSharedMemorySize, C_SMEM);
    cudaFuncSetAttribute(dec_kernel,
                         cudaFuncAttributeMaxDynamicSharedMemorySize, D_SMEM);

    int prep_n = Cc * KPAD + CE * Cc;
    prep_kernel<<<(prep_n + 255) / 256, 256>>>(dw, enc_w);

    dim3 g1(THW / 256, Bsz);
    enc_kernel<<<g1, 256, E_SMEM>>>(x, eg, eb, em, ev);

    dim3 g2(Hh / 8, Tt, Bsz * Gg);
    corr_kernel<<<g2, 224, C_SMEM>>>(fw);

    dim3 g3(THW / 128 * 2, Bsz);
    dec_kernel<<<g3, 256, D_SMEM>>>(x, dg, db, dm, dv, out);
}

// round 11
// speedup vs baseline: 1.8612x; 1.0698x over previous
#include <cuda_runtime.h>
#include <cuda_bf16.h>
#include <cstdint>

#define Bsz   4
#define Cc    256
#define CE    64
#define Tt    16
#define Hh    56
#define Ww    56
#define HW    3136
#define THW   50176
#define Gg    4
#define K2G   196
#define KPAD  224            // 28 islands of 8 (g*56 + ky*8 + kx, kx<7 valid)
#define EPSI  1e-5f

// Scratch (device globals: allocation-free rule)
__device__ float    g_xenc[(size_t)Bsz * CE * THW];
__device__ uint16_t g_xcorrb[(size_t)Bsz * THW * KPAD];   // [pixel][k''] bf16
__device__ uint16_t g_dwb[Cc * KPAD];                     // dec_w permuted bf16
__device__ uint32_t g_wt[CE * Cc];                        // enc_w tf32 bits

__device__ __forceinline__ void cp_async16(uint32_t smem_addr, const void* gptr, int src_bytes) {
    asm volatile("cp.async.cg.shared.global [%0], [%1], 16, %2;"
                 :: "r"(smem_addr), "l"(gptr), "r"(src_bytes));
}
__device__ __forceinline__ void cp_commit() { asm volatile("cp.async.commit_group;"); }
__device__ __forceinline__ void cp_wait0()  { asm volatile("cp.async.wait_group 0;"); }
__device__ __forceinline__ void cp_wait1()  { asm volatile("cp.async.wait_group 1;"); }
__device__ __forceinline__ void cp_wait2()  { asm volatile("cp.async.wait_group 2;"); }

__device__ __forceinline__ uint32_t tf32rna(float f) {
    uint32_t r; asm("cvt.rna.tf32.f32 %0, %1;" : "=r"(r) : "f"(f)); return r;
}
__device__ __forceinline__ uint32_t bf2(float lo, float hi) {
    uint32_t r; asm("cvt.rn.bf16x2.f32 %0, %1, %2;" : "=r"(r) : "f"(hi), "f"(lo));
    return r;
}
__device__ __forceinline__ uint32_t smem_u32(const void* p) {
    return (uint32_t)__cvta_generic_to_shared(p);
}
__device__ __forceinline__ void mma_tf32(float* c, const uint32_t* a, const uint32_t* b) {
    asm volatile(
        "mma.sync.aligned.m16n8k8.row.col.f32.tf32.tf32.f32 "
        "{%0,%1,%2,%3}, {%4,%5,%6,%7}, {%8,%9}, {%0,%1,%2,%3};"
        : "+f"(c[0]), "+f"(c[1]), "+f"(c[2]), "+f"(c[3])
        : "r"(a[0]), "r"(a[1]), "r"(a[2]), "r"(a[3]), "r"(b[0]), "r"(b[1]));
}
__device__ __forceinline__ void mma_bf16(float* c, const uint32_t* a, const uint32_t* b) {
    asm volatile(
        "mma.sync.aligned.m16n8k16.row.col.f32.bf16.bf16.f32 "
        "{%0,%1,%2,%3}, {%4,%5,%6,%7}, {%8,%9}, {%0,%1,%2,%3};"
        : "+f"(c[0]), "+f"(c[1]), "+f"(c[2]), "+f"(c[3])
        : "r"(a[0]), "r"(a[1]), "r"(a[2]), "r"(a[3]), "r"(b[0]), "r"(b[1]));
}
__device__ __forceinline__ void ldsm_x4(uint32_t* r, uint32_t addr) {
    asm volatile("ldmatrix.sync.aligned.m8n8.x4.shared.b16 {%0,%1,%2,%3}, [%4];"
                 : "=r"(r[0]), "=r"(r[1]), "=r"(r[2]), "=r"(r[3]) : "r"(addr));
}
// tf32 f32-tile swizzle (enc)
__device__ __forceinline__ int swoff(int r, int k) {
    return r * 32 + ((((k >> 2) ^ r) & 7) << 2) + (k & 3);
}

// ---------------------------------------------------------------------------
// Kernel 0: prep — dec_w -> bf16 islands; enc_w -> tf32 bits
// ---------------------------------------------------------------------------
__global__ void prep_kernel(const float* __restrict__ dw, const float* __restrict__ ew)
{
    int idx = blockIdx.x * 256 + threadIdx.x;
    if (idx < Cc * KPAD) {
        int m = idx / KPAD, kp = idx % KPAD;
        int g = kp / 56, rem = kp % 56;
        int ky = rem / 8, kx = rem % 8;
        float v = 0.f;
        if (kx < 7) v = dw[m * K2G + (ky * 7 + kx) * 4 + g];
        g_dwb[idx] = (uint16_t)(bf2(v, 0.f) & 0xFFFF);
    } else if (idx < Cc * KPAD + CE * Cc) {
        int j = idx - Cc * KPAD;
        g_wt[j] = tf32rna(ew[j]);
    }
}

// ---------------------------------------------------------------------------
// Kernel 1: enc 1x1 conv on mma.sync tf32 (unchanged, measured ~75us)
// ---------------------------------------------------------------------------
#define E_SMEM (2 * (8192 + 32768))
#define E_AST(s) ((s) * 8192)
#define E_BST(s) (16384 + (s) * 32768)

__global__ void __launch_bounds__(256, 2) enc_kernel(
    const float* __restrict__ x,
    const float* __restrict__ eg, const float* __restrict__ eb,
    const float* __restrict__ em, const float* __restrict__ ev)
{
    extern __shared__ char esm[];
    const int t = threadIdx.x;
    const int wid = t >> 5, lane = t & 31;
    const int warpN = wid;
    const int n0 = blockIdx.x * 256;
    const int b  = blockIdx.y;

    const float* xb = x + (size_t)b * Cc * THW;

    float cacc[4][4][4];
    #pragma unroll
    for (int i = 0; i < 4; i++)
        #pragma unroll
        for (int j = 0; j < 4; j++)
            #pragma unroll
            for (int r = 0; r < 4; r++) cacc[i][j][r] = 0.f;

    int bpos[4];
    #pragma unroll
    for (int nt = 0; nt < 4; nt++) {
        int n = warpN * 32 + nt * 8 + (lane >> 2);
        bpos[nt] = (((n >> 2) ^ (2 * (lane & 3))) << 2) + (n & 3);
    }

    auto load_chunk = [&](int kc, int s) {
        {
            int e = t, r = e >> 3, c = e & 7;
            cp_async16(smem_u32(esm + E_AST(s) + r * 128 + (((c ^ r) & 7) << 4)),
                       g_wt + r * Cc + kc * 32 + c * 4, 16);
            e = t + 256; r = e >> 3; c = e & 7;
            cp_async16(smem_u32(esm + E_AST(s) + r * 128 + (((c ^ r) & 7) << 4)),
                       g_wt + r * Cc + kc * 32 + c * 4, 16);
        }
        #pragma unroll
        for (int i = 0; i < 8; i++) {
            int e = t + 256 * i;
            int k = e >> 6, j = e & 63;
            uint32_t dst = smem_u32(esm + E_BST(s) + k * 1024
                                    + ((j ^ (2 * (k & 3))) << 4));
            cp_async16(dst, xb + (size_t)(kc * 32 + k) * THW + n0 + j * 4, 16);
        }
    };

    load_chunk(0, 0);
    cp_commit();

    for (int c = 0; c < 8; c++) {
        const int s = c & 1;
        if (c > 0) __syncthreads();
        if (c + 1 < 8) { load_chunk(c + 1, s ^ 1); cp_commit(); cp_wait1(); }
        else cp_wait0();
        __syncthreads();

        const uint32_t* Ab = reinterpret_cast<const uint32_t*>(esm + E_AST(s));
        const uint32_t* Bb = reinterpret_cast<const uint32_t*>(esm + E_BST(s));

        #pragma unroll
        for (int ks = 0; ks < 4; ks++) {
            const int kf = ks * 8 + (lane & 3);
            uint32_t bfr[4][2];
            #pragma unroll
            for (int nt = 0; nt < 4; nt++) {
                bfr[nt][0] = tf32rna(__uint_as_float(Bb[kf * 256 + bpos[nt]]));
                bfr[nt][1] = tf32rna(__uint_as_float(Bb[(kf + 4) * 256 + bpos[nt]]));
            }
            #pragma unroll
            for (int mt = 0; mt < 4; mt++) {
                int r = mt * 16 + (lane >> 2);
                uint32_t afr[4];
                afr[0] = Ab[swoff(r,     kf)];
                afr[1] = Ab[swoff(r + 8, kf)];
                afr[2] = Ab[swoff(r,     kf + 4)];
                afr[3] = Ab[swoff(r + 8, kf + 4)];
                #pragma unroll
                for (int nt = 0; nt < 4; nt++)
                    mma_tf32(cacc[mt][nt], afr, bfr[nt]);
            }
        }
    }

    #pragma unroll
    for (int mt = 0; mt < 4; mt++) {
        int ce0 = mt * 16 + (lane >> 2);
        float inv0  = eg[ce0] * rsqrtf(ev[ce0] + EPSI);
        float bias0 = eb[ce0] - em[ce0] * inv0;
        float inv1  = eg[ce0 + 8] * rsqrtf(ev[ce0 + 8] + EPSI);
        float bias1 = eb[ce0 + 8] - em[ce0 + 8] * inv1;
        float* op0 = g_xenc + ((size_t)b * CE + ce0)     * THW + n0;
        float* op1 = g_xenc + ((size_t)b * CE + ce0 + 8) * THW + n0;
        #pragma unroll
        for (int nt = 0; nt < 4; nt++) {
            int n = warpN * 32 + nt * 8 + (lane & 3) * 2;
            float2 o0, o1;
            o0.x = fmaxf(cacc[mt][nt][0] * inv0 + bias0, 0.f);
            o0.y = fmaxf(cacc[mt][nt][1] * inv0 + bias0, 0.f);
            o1.x = fmaxf(cacc[mt][nt][2] * inv1 + bias1, 0.f);
            o1.y = fmaxf(cacc[mt][nt][3] * inv1 + bias1, 0.f);
            *reinterpret_cast<float2*>(op0 + n) = o0;
            *reinterpret_cast<float2*>(op1 + n) = o1;
        }
    }
}

// ---------------------------------------------------------------------------
// Kernel 2: corr v4 — bf16 smem tiles (36-word row stride, conflict-free),
// r = tid&7 / q = tid>>3 mapping, 3 CTAs/SM, 2 px/thread, ky-outer.
// word layout (u32 units): x1[16][8][36] @0, x2[16][14][36] @4608,
//   w f32 [16][7][8] @12672, stage f32 [3136] @13568 -> 16704 w = 66816 B
// ---------------------------------------------------------------------------
#define C_SMEM 66816
#define CX1W(ce, r)    ((ce) * 288 + (r) * 36)
#define CX2W(ce, row)  (4608 + (ce) * 504 + (row) * 36)
#define CWF(ce, ky, k) (12672 + (ce) * 56 + (ky) * 8 + (k))
#define CSTG(j)        (13568 + (j))

__global__ void __launch_bounds__(224, 3) corr_kernel(const float* __restrict__ fw)
{
    extern __shared__ float cs[];
    uint32_t* cw = reinterpret_cast<uint32_t*>(cs);
    const int tid = threadIdx.x;
    const int r   = tid & 7;       // output row within 8-row tile
    const int q   = tid >> 3;      // 0..27
    const int px0 = q * 2;

    const int h0 = blockIdx.x * 8;
    const int tt = blockIdx.y;
    const int b  = blockIdx.z >> 2;
    const int g  = blockIdx.z & 3;
    const int ce0 = g * 16;

    const int t1 = (tt == 0) ? 0 : tt - 1;
    const float* x1base = g_xenc + (size_t)b * CE * THW + (size_t)t1 * HW;
    const float* x2base = g_xenc + (size_t)b * CE * THW + (size_t)tt * HW;
    const size_t pixbase = (size_t)b * THW + (size_t)tt * HW + (size_t)h0 * Ww;

    // weights (f32)
    for (int i = tid; i < 16 * 49; i += 224) {
        int ce = i / 49, tap = i % 49;
        cs[CWF(ce, tap / 7, tap % 7)] = fw[((size_t)(ce0 + ce) * Tt + tt) * 49 + tap];
    }
    // x1 -> bf16 pairs: 16 ce x 8 rows x 28 words
    for (int i = tid; i < 16 * 224; i += 224) {
        int ce = i / 224, rem = i % 224;
        int rr = rem / 28, wi = rem % 28;
        float2 v = *reinterpret_cast<const float2*>(
            x1base + (size_t)(ce0 + ce) * THW + (h0 + rr) * Ww + wi * 2);
        cw[CX1W(ce, rr) + wi] = bf2(v.x, v.y);
    }
    // x2 halo -> bf16 pairs: 16 ce x 14 rows x 32 words (cols -3..60)
    for (int i = tid; i < 16 * 448; i += 224) {
        int ce = i / 448, rem = i % 448;
        int row = rem / 32, wi = rem % 32;
        int hy = h0 + row - 3;
        int c0 = wi * 2 - 3;
        float v0 = 0.f, v1 = 0.f;
        if (hy >= 0 && hy < Hh) {
            const float* p = x2base + (size_t)(ce0 + ce) * THW + hy * Ww;
            if (c0 >= 0 && c0 < Ww) v0 = p[c0];
            if (c0 + 1 >= 0 && c0 + 1 < Ww) v1 = p[c0 + 1];
        }
        cw[CX2W(ce, row) + wi] = bf2(v0, v1);
    }
    __syncthreads();

    #pragma unroll 1
    for (int ky = 0; ky < 7; ky++) {
        float acc[7][2];
        #pragma unroll
        for (int kx = 0; kx < 7; kx++) { acc[kx][0] = 0.f; acc[kx][1] = 0.f; }

        const int zr = r + ky;

        #pragma unroll 4
        for (int ce = 0; ce < 16; ce++) {
            uint32_t yv = cw[CX1W(ce, r) + q];
            float y0 = __uint_as_float(yv << 16);
            float y1 = __uint_as_float(yv & 0xFFFF0000u);
            const uint32_t* zp = &cw[CX2W(ce, zr) + q];
            uint32_t z0 = zp[0], z1 = zp[1], z2 = zp[2], z3 = zp[3];
            float z[8];
            z[0] = __uint_as_float(z0 << 16); z[1] = __uint_as_float(z0 & 0xFFFF0000u);
            z[2] = __uint_as_float(z1 << 16); z[3] = __uint_as_float(z1 & 0xFFFF0000u);
            z[4] = __uint_as_float(z2 << 16); z[5] = __uint_as_float(z2 & 0xFFFF0000u);
            z[6] = __uint_as_float(z3 << 16); z[7] = __uint_as_float(z3 & 0xFFFF0000u);
            const float* wp = &cs[CWF(ce, ky, 0)];
            float4 w4 = *reinterpret_cast<const float4*>(wp);
            float2 w2 = *reinterpret_cast<const float2*>(wp + 4);
            float  w6 = wp[6];
            float w[7] = {w4.x, w4.y, w4.z, w4.w, w2.x, w2.y, w6};
            #pragma unroll
            for (int kx = 0; kx < 7; kx++) {
                acc[kx][0] += w[kx] * (y0 * z[kx]);
                acc[kx][1] += w[kx] * (y1 * z[kx + 1]);
            }
        }

        #pragma unroll
        for (int p = 0; p < 2; p++)
            #pragma unroll
            for (int kx = 0; kx < 7; kx++)
                cs[CSTG((r * 56 + px0 + p) * 7 + kx)] = acc[kx][p] * (1.f / 16.f);
        __syncthreads();

        // bf16 island store: one 16B write per pixel (g*56 + ky*8 + 0..7)
        {
            uint16_t* gb = g_xcorrb + (size_t)g * 56 + (size_t)ky * 8;
            for (int i = tid; i < 448; i += 224) {
                const float* sp = &cs[CSTG(i * 7)];
                uint4 v;
                v.x = bf2(sp[0], sp[1]);
                v.y = bf2(sp[2], sp[3]);
                v.z = bf2(sp[4], sp[5]);
                v.w = bf2(sp[6], 0.f);
                *reinterpret_cast<uint4*>(gb + (pixbase + i) * KPAD) = v;
            }
        }
        __syncthreads();
    }
}

// ---------------------------------------------------------------------------
// Kernel 3: dec GEMM on mma.sync.m16n8k16 bf16 + ldmatrix fragment loads.
// BM=128, BN=128, 256 thr, 8 warps (2m x 4n), warp tile 64x32, 3-stage
// cp.async, 2 CTAs/SM, m-pair grid interleave.
// ---------------------------------------------------------------------------
#define D_SMEM (3 * 16384)
#define D_AST(s) ((s) * 16384)
#define D_BST(s) ((s) * 16384 + 8192)

__global__ void __launch_bounds__(256, 2) dec_kernel(
    const float* __restrict__ x,
    const float* __restrict__ dg, const float* __restrict__ db,
    const float* __restrict__ dm, const float* __restrict__ dv,
    float* __restrict__ out)
{
    extern __shared__ char dsm[];
    const int t    = threadIdx.x;
    const int wid  = t >> 5, lane = t & 31;
    const int warpM = wid >> 2;
    const int warpN = wid & 3;

    const int nx = blockIdx.x >> 1;
    const int m0 = (blockIdx.x & 1) * 128;
    const int b  = blockIdx.y;

    const uint16_t* arow = g_dwb + (size_t)m0 * KPAD;
    const uint16_t* brow = g_xcorrb + ((size_t)b * THW + (size_t)nx * 128) * KPAD;

    float cacc[4][4][4];
    #pragma unroll
    for (int i = 0; i < 4; i++)
        #pragma unroll
        for (int j = 0; j < 4; j++)
            #pragma unroll
            for (int r = 0; r < 4; r++) cacc[i][j][r] = 0.f;

    // ldmatrix lane geometry (loop-invariant parts)
    const int rowBl = warpN * 32 + lane;                       // B: lane == row
    const int swzB  = ((rowBl >> 1) & 3) << 2;
    const int rAoff = (lane & 7) + ((lane >> 3) & 1) * 8;      // A row within mt tile
    const int khA   = ((lane >> 4) & 1) * 4;                   // A k-half word offset

    auto load_chunk = [&](int kc, int s) {
        #pragma unroll
        for (int i = 0; i < 2; i++) {
            int e = t + 256 * i;           // 0..511
            int row = e >> 2, c = e & 3;
            uint32_t soff = row * 64 + ((c ^ ((row >> 1) & 3)) << 4);
            cp_async16(smem_u32(dsm + D_AST(s) + soff),
                       arow + (size_t)row * KPAD + kc * 32 + c * 8, 16);
            cp_async16(smem_u32(dsm + D_BST(s) + soff),
                       brow + (size_t)row * KPAD + kc * 32 + c * 8, 16);
        }
    };

    load_chunk(0, 0); cp_commit();
    load_chunk(1, 1); cp_commit();

    for (int c = 0; c < 7; c++) {
        const int s = c % 3;
        if (c > 0) __syncthreads();
        if (c + 2 < 7) { load_chunk(c + 2, (c + 2) % 3); cp_commit(); }
        if (c < 5) cp_wait2(); else if (c == 5) cp_wait1(); else cp_wait0();
        __syncthreads();

        const uint32_t* Ab = reinterpret_cast<const uint32_t*>(dsm + D_AST(s));
        const uint32_t* Bb = reinterpret_cast<const uint32_t*>(dsm + D_BST(s));

        #pragma unroll
        for (int ks = 0; ks < 2; ks++) {
            const int kb = ks * 8;
            uint32_t bh0[4], bh1[4];
            ldsm_x4(bh0, smem_u32(Bb + rowBl * 16 + (kb ^ swzB)));
            ldsm_x4(bh1, smem_u32(Bb + rowBl * 16 + ((kb + 4) ^ swzB)));
            #pragma unroll
            for (int mt = 0; mt < 4; mt++) {
                int rowA = warpM * 64 + mt * 16 + rAoff;
                int wA = (kb + khA) ^ (((rowA >> 1) & 3) << 2);
                uint32_t afr[4];
                ldsm_x4(afr, smem_u32(Ab + rowA * 16 + wA));
                #pragma unroll
                for (int nt = 0; nt < 4; nt++) {
                    uint32_t bfr[2] = {bh0[nt], bh1[nt]};
                    mma_bf16(cacc[mt][nt], afr, bfr);
                }
            }
        }
    }

    const size_t nbase = (size_t)nx * 128;
    #pragma unroll
    for (int mt = 0; mt < 4; mt++) {
        int mrow = m0 + warpM * 64 + mt * 16 + (lane >> 2);
        float inv0  = dg[mrow] * rsqrtf(dv[mrow] + EPSI);
        float bias0 = db[mrow] - dm[mrow] * inv0;
        float inv1  = dg[mrow + 8] * rsqrtf(dv[mrow + 8] + EPSI);
        float bias1 = db[mrow + 8] - dm[mrow + 8] * inv1;
        const float* xr0 = x   + ((size_t)b * Cc + mrow)     * THW + nbase;
        const float* xr1 = x   + ((size_t)b * Cc + mrow + 8) * THW + nbase;
        float*       op0 = out + ((size_t)b * Cc + mrow)     * THW + nbase;
        float*       op1 = out + ((size_t)b * Cc + mrow + 8) * THW + nbase;
        #pragma unroll
        for (int nt = 0; nt < 4; nt++) {
            int n = warpN * 32 + nt * 8 + (lane & 3) * 2;
            float2 r0 = *reinterpret_cast<const float2*>(xr0 + n);
            float2 r1 = *reinterpret_cast<const float2*>(xr1 + n);
            float2 o0, o1;
            o0.x = fmaxf(cacc[mt][nt][0] * inv0 + bias0 + r0.x, 0.f);
            o0.y = fmaxf(cacc[mt][nt][1] * inv0 + bias0 + r0.y, 0.f);
            o1.x = fmaxf(cacc[mt][nt][2] * inv1 + bias1 + r1.x, 0.f);
            o1.y = fmaxf(cacc[mt][nt][3] * inv1 + bias1 + r1.y, 0.f);
            *reinterpret_cast<float2*>(op0 + n) = o0;
            *reinterpret_cast<float2*>(op1 + n) = o1;
        }
    }
}

// ---------------------------------------------------------------------------
extern "C" void kernel_launch(void* const* d_in, const int* in_sizes, int n_in,
                              void* d_out, int out_size)
{
    const float* x     = (const float*)d_in[0];
    const float* enc_w = (const float*)d_in[1];
    const float* eg    = (const float*)d_in[2];
    const float* eb    = (const float*)d_in[3];
    const float* em    = (const float*)d_in[4];
    const float* ev    = (const float*)d_in[5];
    const float* fw    = (const float*)d_in[6];
    const float* dw    = (const float*)d_in[7];
    const float* dg    = (const float*)d_in[8];
    const float* db    = (const float*)d_in[9];
    const float* dm    = (const float*)d_in[10];
    const float* dv    = (const float*)d_in[11];
    float* out = (float*)d_out;

    cudaFuncSetAttribute(enc_kernel,
                         cudaFuncAttributeMaxDynamicSharedMemorySize, E_SMEM);
    cudaFuncSetAttribute(corr_kernel,
                         cudaFuncAttributeMaxDynamicSharedMemorySize, C_SMEM);
    cudaFuncSetAttribute(dec_kernel,
                         cudaFuncAttributeMaxDynamicSharedMemorySize, D_SMEM);

    int prep_n = Cc * KPAD + CE * Cc;
    prep_kernel<<<(prep_n + 255) / 256, 256>>>(dw, enc_w);

    dim3 g1(THW / 256, Bsz);
    enc_kernel<<<g1, 256, E_SMEM>>>(x, eg, eb, em, ev);

    dim3 g2(Hh / 8, Tt, Bsz * Gg);
    corr_kernel<<<g2, 224, C_SMEM>>>(fw);

    dim3 g3(THW / 128 * 2, Bsz);
    dec_kernel<<<g3, 256, D_SMEM>>>(x, dg, db, dm, dv, out);
}

// round 12
// speedup vs baseline: 2.0598x; 1.1067x over previous
#include <cuda_runtime.h>
#include <cuda_bf16.h>
#include <cstdint>

#define Bsz   4
#define Cc    256
#define CE    64
#define Tt    16
#define Hh    56
#define Ww    56
#define HW    3136
#define THW   50176
#define Gg    4
#define K2G   196
#define KPAD  224            // 28 islands of 8 (g*56 + ky*8 + kx, kx<7 valid)
#define EPSI  1e-5f

// Scratch (device globals: allocation-free rule)
__device__ uint16_t g_xencb[(size_t)Bsz * CE * THW];      // x_enc bf16
__device__ uint16_t g_xcorrb[(size_t)Bsz * THW * KPAD];   // [pixel][k''] bf16
__device__ uint16_t g_dwb[Cc * KPAD];                     // dec_w permuted bf16
__device__ uint32_t g_wt[CE * Cc];                        // enc_w tf32 bits

__device__ __forceinline__ void cp_async16(uint32_t smem_addr, const void* gptr, int src_bytes) {
    asm volatile("cp.async.cg.shared.global [%0], [%1], 16, %2;"
                 :: "r"(smem_addr), "l"(gptr), "r"(src_bytes));
}
__device__ __forceinline__ void cp_commit() { asm volatile("cp.async.commit_group;"); }
__device__ __forceinline__ void cp_wait0()  { asm volatile("cp.async.wait_group 0;"); }
__device__ __forceinline__ void cp_wait1()  { asm volatile("cp.async.wait_group 1;"); }
__device__ __forceinline__ void cp_wait2()  { asm volatile("cp.async.wait_group 2;"); }

__device__ __forceinline__ uint32_t tf32rna(float f) {
    uint32_t r; asm("cvt.rna.tf32.f32 %0, %1;" : "=r"(r) : "f"(f)); return r;
}
__device__ __forceinline__ uint32_t bf2(float lo, float hi) {
    uint32_t r; asm("cvt.rn.bf16x2.f32 %0, %1, %2;" : "=r"(r) : "f"(hi), "f"(lo));
    return r;
}
__device__ __forceinline__ float bflo(uint32_t w) { return __uint_as_float(w << 16); }
__device__ __forceinline__ float bfhi(uint32_t w) { return __uint_as_float(w & 0xFFFF0000u); }
__device__ __forceinline__ uint32_t smem_u32(const void* p) {
    return (uint32_t)__cvta_generic_to_shared(p);
}
__device__ __forceinline__ void mma_tf32(float* c, const uint32_t* a, const uint32_t* b) {
    asm volatile(
        "mma.sync.aligned.m16n8k8.row.col.f32.tf32.tf32.f32 "
        "{%0,%1,%2,%3}, {%4,%5,%6,%7}, {%8,%9}, {%0,%1,%2,%3};"
        : "+f"(c[0]), "+f"(c[1]), "+f"(c[2]), "+f"(c[3])
        : "r"(a[0]), "r"(a[1]), "r"(a[2]), "r"(a[3]), "r"(b[0]), "r"(b[1]));
}
__device__ __forceinline__ void mma_bf16(float* c, const uint32_t* a, const uint32_t* b) {
    asm volatile(
        "mma.sync.aligned.m16n8k16.row.col.f32.bf16.bf16.f32 "
        "{%0,%1,%2,%3}, {%4,%5,%6,%7}, {%8,%9}, {%0,%1,%2,%3};"
        : "+f"(c[0]), "+f"(c[1]), "+f"(c[2]), "+f"(c[3])
        : "r"(a[0]), "r"(a[1]), "r"(a[2]), "r"(a[3]), "r"(b[0]), "r"(b[1]));
}
__device__ __forceinline__ void ldsm_x4(uint32_t* r, uint32_t addr) {
    asm volatile("ldmatrix.sync.aligned.m8n8.x4.shared.b16 {%0,%1,%2,%3}, [%4];"
                 : "=r"(r[0]), "=r"(r[1]), "=r"(r[2]), "=r"(r[3]) : "r"(addr));
}
// tf32 f32-tile swizzle (enc)
__device__ __forceinline__ int swoff(int r, int k) {
    return r * 32 + ((((k >> 2) ^ r) & 7) << 2) + (k & 3);
}

// ---------------------------------------------------------------------------
// Kernel 0: prep — dec_w -> bf16 islands; enc_w -> tf32 bits
// ---------------------------------------------------------------------------
__global__ void prep_kernel(const float* __restrict__ dw, const float* __restrict__ ew)
{
    int idx = blockIdx.x * 256 + threadIdx.x;
    if (idx < Cc * KPAD) {
        int m = idx / KPAD, kp = idx % KPAD;
        int g = kp / 56, rem = kp % 56;
        int ky = rem / 8, kx = rem % 8;
        float v = 0.f;
        if (kx < 7) v = dw[m * K2G + (ky * 7 + kx) * 4 + g];
        g_dwb[idx] = (uint16_t)(bf2(v, 0.f) & 0xFFFF);
    } else if (idx < Cc * KPAD + CE * Cc) {
        int j = idx - Cc * KPAD;
        g_wt[j] = tf32rna(ew[j]);
    }
}

// ---------------------------------------------------------------------------
// Kernel 1: enc 1x1 conv on mma.sync tf32; epilogue writes bf16 x_enc.
// ---------------------------------------------------------------------------
#define E_SMEM (2 * (8192 + 32768))
#define E_AST(s) ((s) * 8192)
#define E_BST(s) (16384 + (s) * 32768)

__global__ void __launch_bounds__(256, 2) enc_kernel(
    const float* __restrict__ x,
    const float* __restrict__ eg, const float* __restrict__ eb,
    const float* __restrict__ em, const float* __restrict__ ev)
{
    extern __shared__ char esm[];
    const int t = threadIdx.x;
    const int wid = t >> 5, lane = t & 31;
    const int warpN = wid;
    const int n0 = blockIdx.x * 256;
    const int b  = blockIdx.y;

    const float* xb = x + (size_t)b * Cc * THW;

    float cacc[4][4][4];
    #pragma unroll
    for (int i = 0; i < 4; i++)
        #pragma unroll
        for (int j = 0; j < 4; j++)
            #pragma unroll
            for (int r = 0; r < 4; r++) cacc[i][j][r] = 0.f;

    int bpos[4];
    #pragma unroll
    for (int nt = 0; nt < 4; nt++) {
        int n = warpN * 32 + nt * 8 + (lane >> 2);
        bpos[nt] = (((n >> 2) ^ (2 * (lane & 3))) << 2) + (n & 3);
    }

    auto load_chunk = [&](int kc, int s) {
        {
            int e = t, r = e >> 3, c = e & 7;
            cp_async16(smem_u32(esm + E_AST(s) + r * 128 + (((c ^ r) & 7) << 4)),
                       g_wt + r * Cc + kc * 32 + c * 4, 16);
            e = t + 256; r = e >> 3; c = e & 7;
            cp_async16(smem_u32(esm + E_AST(s) + r * 128 + (((c ^ r) & 7) << 4)),
                       g_wt + r * Cc + kc * 32 + c * 4, 16);
        }
        #pragma unroll
        for (int i = 0; i < 8; i++) {
            int e = t + 256 * i;
            int k = e >> 6, j = e & 63;
            uint32_t dst = smem_u32(esm + E_BST(s) + k * 1024
                                    + ((j ^ (2 * (k & 3))) << 4));
            cp_async16(dst, xb + (size_t)(kc * 32 + k) * THW + n0 + j * 4, 16);
        }
    };

    load_chunk(0, 0);
    cp_commit();

    for (int c = 0; c < 8; c++) {
        const int s = c & 1;
        if (c > 0) __syncthreads();
        if (c + 1 < 8) { load_chunk(c + 1, s ^ 1); cp_commit(); cp_wait1(); }
        else cp_wait0();
        __syncthreads();

        const uint32_t* Ab = reinterpret_cast<const uint32_t*>(esm + E_AST(s));
        const uint32_t* Bb = reinterpret_cast<const uint32_t*>(esm + E_BST(s));

        #pragma unroll
        for (int ks = 0; ks < 4; ks++) {
            const int kf = ks * 8 + (lane & 3);
            uint32_t bfr[4][2];
            #pragma unroll
            for (int nt = 0; nt < 4; nt++) {
                bfr[nt][0] = tf32rna(__uint_as_float(Bb[kf * 256 + bpos[nt]]));
                bfr[nt][1] = tf32rna(__uint_as_float(Bb[(kf + 4) * 256 + bpos[nt]]));
            }
            #pragma unroll
            for (int mt = 0; mt < 4; mt++) {
                int r = mt * 16 + (lane >> 2);
                uint32_t afr[4];
                afr[0] = Ab[swoff(r,     kf)];
                afr[1] = Ab[swoff(r + 8, kf)];
                afr[2] = Ab[swoff(r,     kf + 4)];
                afr[3] = Ab[swoff(r + 8, kf + 4)];
                #pragma unroll
                for (int nt = 0; nt < 4; nt++)
                    mma_tf32(cacc[mt][nt], afr, bfr[nt]);
            }
        }
    }

    #pragma unroll
    for (int mt = 0; mt < 4; mt++) {
        int ce0 = mt * 16 + (lane >> 2);
        float inv0  = eg[ce0] * rsqrtf(ev[ce0] + EPSI);
        float bias0 = eb[ce0] - em[ce0] * inv0;
        float inv1  = eg[ce0 + 8] * rsqrtf(ev[ce0 + 8] + EPSI);
        float bias1 = eb[ce0 + 8] - em[ce0 + 8] * inv1;
        uint32_t* op0 = reinterpret_cast<uint32_t*>(
            g_xencb + ((size_t)b * CE + ce0)     * THW + n0);
        uint32_t* op1 = reinterpret_cast<uint32_t*>(
            g_xencb + ((size_t)b * CE + ce0 + 8) * THW + n0);
        #pragma unroll
        for (int nt = 0; nt < 4; nt++) {
            int n = warpN * 32 + nt * 8 + (lane & 3) * 2;
            float a0 = fmaxf(cacc[mt][nt][0] * inv0 + bias0, 0.f);
            float a1 = fmaxf(cacc[mt][nt][1] * inv0 + bias0, 0.f);
            float a2 = fmaxf(cacc[mt][nt][2] * inv1 + bias1, 0.f);
            float a3 = fmaxf(cacc[mt][nt][3] * inv1 + bias1, 0.f);
            op0[n >> 1] = bf2(a0, a1);
            op1[n >> 1] = bf2(a2, a3);
        }
    }
}

// ---------------------------------------------------------------------------
// Kernel 2: corr v5 — bf16 x_enc input (direct u32 fills, halo base -4),
// bf16 smem tiles, 3 CTAs/SM, 2 px/thread, ky-outer.
// word layout (u32): x1[16][8][36] @0, x2[16][14][36] @4608 (cols -4..59),
//   w f32 [16][7][8] @12672, stage f32 [3136] @13568 -> 66816 B
// ---------------------------------------------------------------------------
#define C_SMEM 66816
#define CX1W(ce, r)    ((ce) * 288 + (r) * 36)
#define CX2W(ce, row)  (4608 + (ce) * 504 + (row) * 36)
#define CWF(ce, ky, k) (12672 + (ce) * 56 + (ky) * 8 + (k))
#define CSTG(j)        (13568 + (j))

__global__ void __launch_bounds__(224, 3) corr_kernel(const float* __restrict__ fw)
{
    extern __shared__ float cs[];
    uint32_t* cw = reinterpret_cast<uint32_t*>(cs);
    const int tid = threadIdx.x;
    const int r   = tid & 7;       // output row within 8-row tile
    const int q   = tid >> 3;      // 0..27
    const int px0 = q * 2;

    const int h0 = blockIdx.x * 8;
    const int tt = blockIdx.y;
    const int b  = blockIdx.z >> 2;
    const int g  = blockIdx.z & 3;
    const int ce0 = g * 16;

    const int t1 = (tt == 0) ? 0 : tt - 1;
    const uint16_t* x1b = g_xencb + (size_t)b * CE * THW + (size_t)t1 * HW;
    const uint16_t* x2b = g_xencb + (size_t)b * CE * THW + (size_t)tt * HW;
    const size_t pixbase = (size_t)b * THW + (size_t)tt * HW + (size_t)h0 * Ww;

    // weights (f32)
    for (int i = tid; i < 16 * 49; i += 224) {
        int ce = i / 49, tap = i % 49;
        cs[CWF(ce, tap / 7, tap % 7)] = fw[((size_t)(ce0 + ce) * Tt + tt) * 49 + tap];
    }
    // x1: 16 ce x 8 rows x 28 words, direct u32 loads
    for (int i = tid; i < 16 * 224; i += 224) {
        int ce = i / 224, rem = i % 224;
        int rr = rem / 28, wi = rem % 28;
        cw[CX1W(ce, rr) + wi] = *reinterpret_cast<const uint32_t*>(
            x1b + (size_t)(ce0 + ce) * THW + (h0 + rr) * Ww + wi * 2);
    }
    // x2 halo: 16 ce x 14 rows x 32 words, cols -4..59; word fully valid or 0
    for (int i = tid; i < 16 * 448; i += 224) {
        int ce = i / 448, rem = i % 448;
        int row = rem / 32, wi = rem % 32;
        int hy = h0 + row - 3;
        int c0 = wi * 2 - 4;
        uint32_t v = 0;
        if (hy >= 0 && hy < Hh && wi >= 2 && wi <= 29)
            v = *reinterpret_cast<const uint32_t*>(
                x2b + (size_t)(ce0 + ce) * THW + hy * Ww + c0);
        cw[CX2W(ce, row) + wi] = v;
    }
    __syncthreads();

    #pragma unroll 1
    for (int ky = 0; ky < 7; ky++) {
        float acc[7][2];
        #pragma unroll
        for (int kx = 0; kx < 7; kx++) { acc[kx][0] = 0.f; acc[kx][1] = 0.f; }

        const int zr = r + ky;

        #pragma unroll 4
        for (int ce = 0; ce < 16; ce++) {
            uint32_t yv = cw[CX1W(ce, r) + q];
            float y0 = bflo(yv), y1 = bfhi(yv);
            const uint32_t* zp = &cw[CX2W(ce, zr) + q];
            uint32_t zw0 = zp[0], zw1 = zp[1], zw2 = zp[2], zw3 = zp[3], zw4 = zp[4];
            // element m (= p+kx): col 2q-3+m
            float z[8];
            z[0] = bfhi(zw0);
            z[1] = bflo(zw1); z[2] = bfhi(zw1);
            z[3] = bflo(zw2); z[4] = bfhi(zw2);
            z[5] = bflo(zw3); z[6] = bfhi(zw3);
            z[7] = bflo(zw4);
            const float* wp = &cs[CWF(ce, ky, 0)];
            float4 w4 = *reinterpret_cast<const float4*>(wp);
            float2 w2 = *reinterpret_cast<const float2*>(wp + 4);
            float  w6 = wp[6];
            float w[7] = {w4.x, w4.y, w4.z, w4.w, w2.x, w2.y, w6};
            #pragma unroll
            for (int kx = 0; kx < 7; kx++) {
                acc[kx][0] += w[kx] * (y0 * z[kx]);
                acc[kx][1] += w[kx] * (y1 * z[kx + 1]);
            }
        }

        #pragma unroll
        for (int p = 0; p < 2; p++)
            #pragma unroll
            for (int kx = 0; kx < 7; kx++)
                cs[CSTG((r * 56 + px0 + p) * 7 + kx)] = acc[kx][p] * (1.f / 16.f);
        __syncthreads();

        // bf16 island store: one 16B write per pixel (g*56 + ky*8 + 0..7)
        {
            uint16_t* gb = g_xcorrb + (size_t)g * 56 + (size_t)ky * 8;
            for (int i = tid; i < 448; i += 224) {
                const float* sp = &cs[CSTG(i * 7)];
                uint4 v;
                v.x = bf2(sp[0], sp[1]);
                v.y = bf2(sp[2], sp[3]);
                v.z = bf2(sp[4], sp[5]);
                v.w = bf2(sp[6], 0.f);
                *reinterpret_cast<uint4*>(gb + (pixbase + i) * KPAD) = v;
            }
        }
        __syncthreads();
    }
}

// ---------------------------------------------------------------------------
// Kernel 3: dec GEMM on mma.sync.m16n8k16 bf16 + ldmatrix (unchanged R11).
// ---------------------------------------------------------------------------
#define D_SMEM (3 * 16384)
#define D_AST(s) ((s) * 16384)
#define D_BST(s) ((s) * 16384 + 8192)

__global__ void __launch_bounds__(256, 2) dec_kernel(
    const float* __restrict__ x,
    const float* __restrict__ dg, const float* __restrict__ db,
    const float* __restrict__ dm, const float* __restrict__ dv,
    float* __restrict__ out)
{
    extern __shared__ char dsm[];
    const int t    = threadIdx.x;
    const int wid  = t >> 5, lane = t & 31;
    const int warpM = wid >> 2;
    const int warpN = wid & 3;

    const int nx = blockIdx.x >> 1;
    const int m0 = (blockIdx.x & 1) * 128;
    const int b  = blockIdx.y;

    const uint16_t* arow = g_dwb + (size_t)m0 * KPAD;
    const uint16_t* brow = g_xcorrb + ((size_t)b * THW + (size_t)nx * 128) * KPAD;

    float cacc[4][4][4];
    #pragma unroll
    for (int i = 0; i < 4; i++)
        #pragma unroll
        for (int j = 0; j < 4; j++)
            #pragma unroll
            for (int r = 0; r < 4; r++) cacc[i][j][r] = 0.f;

    const int rowBl = warpN * 32 + lane;
    const int swzB  = ((rowBl >> 1) & 3) << 2;
    const int rAoff = (lane & 7) + ((lane >> 3) & 1) * 8;
    const int khA   = ((lane >> 4) & 1) * 4;

    auto load_chunk = [&](int kc, int s) {
        #pragma unroll
        for (int i = 0; i < 2; i++) {
            int e = t + 256 * i;
            int row = e >> 2, c = e & 3;
            uint32_t soff = row * 64 + ((c ^ ((row >> 1) & 3)) << 4);
            cp_async16(smem_u32(dsm + D_AST(s) + soff),
                       arow + (size_t)row * KPAD + kc * 32 + c * 8, 16);
            cp_async16(smem_u32(dsm + D_BST(s) + soff),
                       brow + (size_t)row * KPAD + kc * 32 + c * 8, 16);
        }
    };

    load_chunk(0, 0); cp_commit();
    load_chunk(1, 1); cp_commit();

    for (int c = 0; c < 7; c++) {
        const int s = c % 3;
        if (c > 0) __syncthreads();
        if (c + 2 < 7) { load_chunk(c + 2, (c + 2) % 3); cp_commit(); }
        if (c < 5) cp_wait2(); else if (c == 5) cp_wait1(); else cp_wait0();
        __syncthreads();

        const uint32_t* Ab = reinterpret_cast<const uint32_t*>(dsm + D_AST(s));
        const uint32_t* Bb = reinterpret_cast<const uint32_t*>(dsm + D_BST(s));

        #pragma unroll
        for (int ks = 0; ks < 2; ks++) {
            const int kb = ks * 8;
            uint32_t bh0[4], bh1[4];
            ldsm_x4(bh0, smem_u32(Bb + rowBl * 16 + (kb ^ swzB)));
            ldsm_x4(bh1, smem_u32(Bb + rowBl * 16 + ((kb + 4) ^ swzB)));
            #pragma unroll
            for (int mt = 0; mt < 4; mt++) {
                int rowA = warpM * 64 + mt * 16 + rAoff;
                int wA = (kb + khA) ^ (((rowA >> 1) & 3) << 2);
                uint32_t afr[4];
                ldsm_x4(afr, smem_u32(Ab + rowA * 16 + wA));
                #pragma unroll
                for (int nt = 0; nt < 4; nt++) {
                    uint32_t bfr[2] = {bh0[nt], bh1[nt]};
                    mma_bf16(cacc[mt][nt], afr, bfr);
                }
            }
        }
    }

    const size_t nbase = (size_t)nx * 128;
    #pragma unroll
    for (int mt = 0; mt < 4; mt++) {
        int mrow = m0 + warpM * 64 + mt * 16 + (lane >> 2);
        float inv0  = dg[mrow] * rsqrtf(dv[mrow] + EPSI);
        float bias0 = db[mrow] - dm[mrow] * inv0;
        float inv1  = dg[mrow + 8] * rsqrtf(dv[mrow + 8] + EPSI);
        float bias1 = db[mrow + 8] - dm[mrow + 8] * inv1;
        const float* xr0 = x   + ((size_t)b * Cc + mrow)     * THW + nbase;
        const float* xr1 = x   + ((size_t)b * Cc + mrow + 8) * THW + nbase;
        float*       op0 = out + ((size_t)b * Cc + mrow)     * THW + nbase;
        float*       op1 = out + ((size_t)b * Cc + mrow + 8) * THW + nbase;
        #pragma unroll
        for (int nt = 0; nt < 4; nt++) {
            int n = warpN * 32 + nt * 8 + (lane & 3) * 2;
            float2 r0 = *reinterpret_cast<const float2*>(xr0 + n);
            float2 r1 = *reinterpret_cast<const float2*>(xr1 + n);
            float2 o0, o1;
            o0.x = fmaxf(cacc[mt][nt][0] * inv0 + bias0 + r0.x, 0.f);
            o0.y = fmaxf(cacc[mt][nt][1] * inv0 + bias0 + r0.y, 0.f);
            o1.x = fmaxf(cacc[mt][nt][2] * inv1 + bias1 + r1.x, 0.f);
            o1.y = fmaxf(cacc[mt][nt][3] * inv1 + bias1 + r1.y, 0.f);
            *reinterpret_cast<float2*>(op0 + n) = o0;
            *reinterpret_cast<float2*>(op1 + n) = o1;
        }
    }
}

// ---------------------------------------------------------------------------
extern "C" void kernel_launch(void* const* d_in, const int* in_sizes, int n_in,
                              void* d_out, int out_size)
{
    const float* x     = (const float*)d_in[0];
    const float* enc_w = (const float*)d_in[1];
    const float* eg    = (const float*)d_in[2];
    const float* eb    = (const float*)d_in[3];
    const float* em    = (const float*)d_in[4];
    const float* ev    = (const float*)d_in[5];
    const float* fw    = (const float*)d_in[6];
    const float* dw    = (const float*)d_in[7];
    const float* dg    = (const float*)d_in[8];
    const float* db    = (const float*)d_in[9];
    const float* dm    = (const float*)d_in[10];
    const float* dv    = (const float*)d_in[11];
    float* out = (float*)d_out;

    cudaFuncSetAttribute(enc_kernel,
                         cudaFuncAttributeMaxDynamicSharedMemorySize, E_SMEM);
    cudaFuncSetAttribute(corr_kernel,
                         cudaFuncAttributeMaxDynamicSharedMemorySize, C_SMEM);
    cudaFuncSetAttribute(dec_kernel,
                         cudaFuncAttributeMaxDynamicSharedMemorySize, D_SMEM);

    int prep_n = Cc * KPAD + CE * Cc;
    prep_kernel<<<(prep_n + 255) / 256, 256>>>(dw, enc_w);

    dim3 g1(THW / 256, Bsz);
    enc_kernel<<<g1, 256, E_SMEM>>>(x, eg, eb, em, ev);

    dim3 g2(Hh / 8, Tt, Bsz * Gg);
    corr_kernel<<<g2, 224, C_SMEM>>>(fw);

    dim3 g3(THW / 128 * 2, Bsz);
    dec_kernel<<<g3, 256, D_SMEM>>>(x, dg, db, dm, dv, out);
}

// round 13
// speedup vs baseline: 2.2278x; 1.0816x over previous
#include <cuda_runtime.h>
#include <cuda_bf16.h>
#include <cstdint>

#define Bsz   4
#define Cc    256
#define CE    64
#define Tt    16
#define Hh    56
#define Ww    56
#define HW    3136
#define THW   50176
#define Gg    4
#define K2G   196
#define KPAD  224            // 28 islands of 8 (g*56 + ky*8 + kx, kx<7 valid)
#define EPSI  1e-5f

// Scratch (device globals: allocation-free rule)
__device__ uint16_t g_xencb[(size_t)Bsz * CE * THW];      // x_enc bf16
__device__ uint16_t g_xcorrb[(size_t)Bsz * THW * KPAD];   // [pixel][k''] bf16
__device__ uint16_t g_dwb[Cc * KPAD];                     // dec_w permuted bf16
__device__ uint32_t g_wt[CE * Cc];                        // enc_w tf32 bits

__device__ __forceinline__ void cp_async16(uint32_t smem_addr, const void* gptr, int src_bytes) {
    asm volatile("cp.async.cg.shared.global [%0], [%1], 16, %2;"
                 :: "r"(smem_addr), "l"(gptr), "r"(src_bytes));
}
__device__ __forceinline__ void cp_commit() { asm volatile("cp.async.commit_group;"); }
__device__ __forceinline__ void cp_wait0()  { asm volatile("cp.async.wait_group 0;"); }
__device__ __forceinline__ void cp_wait1()  { asm volatile("cp.async.wait_group 1;"); }

__device__ __forceinline__ uint32_t tf32rna(float f) {
    uint32_t r; asm("cvt.rna.tf32.f32 %0, %1;" : "=r"(r) : "f"(f)); return r;
}
__device__ __forceinline__ uint32_t bf2(float lo, float hi) {
    uint32_t r; asm("cvt.rn.bf16x2.f32 %0, %1, %2;" : "=r"(r) : "f"(hi), "f"(lo));
    return r;
}
__device__ __forceinline__ float bflo(uint32_t w) { return __uint_as_float(w << 16); }
__device__ __forceinline__ float bfhi(uint32_t w) { return __uint_as_float(w & 0xFFFF0000u); }
__device__ __forceinline__ uint32_t smem_u32(const void* p) {
    return (uint32_t)__cvta_generic_to_shared(p);
}
__device__ __forceinline__ void mma_tf32(float* c, const uint32_t* a, const uint32_t* b) {
    asm volatile(
        "mma.sync.aligned.m16n8k8.row.col.f32.tf32.tf32.f32 "
        "{%0,%1,%2,%3}, {%4,%5,%6,%7}, {%8,%9}, {%0,%1,%2,%3};"
        : "+f"(c[0]), "+f"(c[1]), "+f"(c[2]), "+f"(c[3])
        : "r"(a[0]), "r"(a[1]), "r"(a[2]), "r"(a[3]), "r"(b[0]), "r"(b[1]));
}
__device__ __forceinline__ void mma_bf16(float* c, const uint32_t* a, const uint32_t* b) {
    asm volatile(
        "mma.sync.aligned.m16n8k16.row.col.f32.bf16.bf16.f32 "
        "{%0,%1,%2,%3}, {%4,%5,%6,%7}, {%8,%9}, {%0,%1,%2,%3};"
        : "+f"(c[0]), "+f"(c[1]), "+f"(c[2]), "+f"(c[3])
        : "r"(a[0]), "r"(a[1]), "r"(a[2]), "r"(a[3]), "r"(b[0]), "r"(b[1]));
}
__device__ __forceinline__ void ldsm_x4(uint32_t* r, uint32_t addr) {
    asm volatile("ldmatrix.sync.aligned.m8n8.x4.shared.b16 {%0,%1,%2,%3}, [%4];"
                 : "=r"(r[0]), "=r"(r[1]), "=r"(r[2]), "=r"(r[3]) : "r"(addr));
}
// tf32 f32-tile swizzle (enc)
__device__ __forceinline__ int swoff(int r, int k) {
    return r * 32 + ((((k >> 2) ^ r) & 7) << 2) + (k & 3);
}

// ---------------------------------------------------------------------------
// Kernel 0: prep — dec_w -> bf16 islands; enc_w -> tf32 bits
// ---------------------------------------------------------------------------
__global__ void prep_kernel(const float* __restrict__ dw, const float* __restrict__ ew)
{
    int idx = blockIdx.x * 256 + threadIdx.x;
    if (idx < Cc * KPAD) {
        int m = idx / KPAD, kp = idx % KPAD;
        int g = kp / 56, rem = kp % 56;
        int ky = rem / 8, kx = rem % 8;
        float v = 0.f;
        if (kx < 7) v = dw[m * K2G + (ky * 7 + kx) * 4 + g];
        g_dwb[idx] = (uint16_t)(bf2(v, 0.f) & 0xFFFF);
    } else if (idx < Cc * KPAD + CE * Cc) {
        int j = idx - Cc * KPAD;
        g_wt[j] = tf32rna(ew[j]);
    }
}

// ---------------------------------------------------------------------------
// Kernel 1: enc 1x1 conv on mma.sync tf32; epilogue writes bf16 x_enc.
// ---------------------------------------------------------------------------
#define E_SMEM (2 * (8192 + 32768))
#define E_AST(s) ((s) * 8192)
#define E_BST(s) (16384 + (s) * 32768)

__global__ void __launch_bounds__(256, 2) enc_kernel(
    const float* __restrict__ x,
    const float* __restrict__ eg, const float* __restrict__ eb,
    const float* __restrict__ em, const float* __restrict__ ev)
{
    extern __shared__ char esm[];
    const int t = threadIdx.x;
    const int wid = t >> 5, lane = t & 31;
    const int warpN = wid;
    const int n0 = blockIdx.x * 256;
    const int b  = blockIdx.y;

    const float* xb = x + (size_t)b * Cc * THW;

    float cacc[4][4][4];
    #pragma unroll
    for (int i = 0; i < 4; i++)
        #pragma unroll
        for (int j = 0; j < 4; j++)
            #pragma unroll
            for (int r = 0; r < 4; r++) cacc[i][j][r] = 0.f;

    int bpos[4];
    #pragma unroll
    for (int nt = 0; nt < 4; nt++) {
        int n = warpN * 32 + nt * 8 + (lane >> 2);
        bpos[nt] = (((n >> 2) ^ (2 * (lane & 3))) << 2) + (n & 3);
    }

    auto load_chunk = [&](int kc, int s) {
        {
            int e = t, r = e >> 3, c = e & 7;
            cp_async16(smem_u32(esm + E_AST(s) + r * 128 + (((c ^ r) & 7) << 4)),
                       g_wt + r * Cc + kc * 32 + c * 4, 16);
            e = t + 256; r = e >> 3; c = e & 7;
            cp_async16(smem_u32(esm + E_AST(s) + r * 128 + (((c ^ r) & 7) << 4)),
                       g_wt + r * Cc + kc * 32 + c * 4, 16);
        }
        #pragma unroll
        for (int i = 0; i < 8; i++) {
            int e = t + 256 * i;
            int k = e >> 6, j = e & 63;
            uint32_t dst = smem_u32(esm + E_BST(s) + k * 1024
                                    + ((j ^ (2 * (k & 3))) << 4));
            cp_async16(dst, xb + (size_t)(kc * 32 + k) * THW + n0 + j * 4, 16);
        }
    };

    load_chunk(0, 0);
    cp_commit();

    for (int c = 0; c < 8; c++) {
        const int s = c & 1;
        if (c > 0) __syncthreads();
        if (c + 1 < 8) { load_chunk(c + 1, s ^ 1); cp_commit(); cp_wait1(); }
        else cp_wait0();
        __syncthreads();

        const uint32_t* Ab = reinterpret_cast<const uint32_t*>(esm + E_AST(s));
        const uint32_t* Bb = reinterpret_cast<const uint32_t*>(esm + E_BST(s));

        #pragma unroll
        for (int ks = 0; ks < 4; ks++) {
            const int kf = ks * 8 + (lane & 3);
            uint32_t bfr[4][2];
            #pragma unroll
            for (int nt = 0; nt < 4; nt++) {
                bfr[nt][0] = tf32rna(__uint_as_float(Bb[kf * 256 + bpos[nt]]));
                bfr[nt][1] = tf32rna(__uint_as_float(Bb[(kf + 4) * 256 + bpos[nt]]));
            }
            #pragma unroll
            for (int mt = 0; mt < 4; mt++) {
                int r = mt * 16 + (lane >> 2);
                uint32_t afr[4];
                afr[0] = Ab[swoff(r,     kf)];
                afr[1] = Ab[swoff(r + 8, kf)];
                afr[2] = Ab[swoff(r,     kf + 4)];
                afr[3] = Ab[swoff(r + 8, kf + 4)];
                #pragma unroll
                for (int nt = 0; nt < 4; nt++)
                    mma_tf32(cacc[mt][nt], afr, bfr[nt]);
            }
        }
    }

    #pragma unroll
    for (int mt = 0; mt < 4; mt++) {
        int ce0 = mt * 16 + (lane >> 2);
        float inv0  = eg[ce0] * rsqrtf(ev[ce0] + EPSI);
        float bias0 = eb[ce0] - em[ce0] * inv0;
        float inv1  = eg[ce0 + 8] * rsqrtf(ev[ce0 + 8] + EPSI);
        float bias1 = eb[ce0 + 8] - em[ce0 + 8] * inv1;
        uint32_t* op0 = reinterpret_cast<uint32_t*>(
            g_xencb + ((size_t)b * CE + ce0)     * THW + n0);
        uint32_t* op1 = reinterpret_cast<uint32_t*>(
            g_xencb + ((size_t)b * CE + ce0 + 8) * THW + n0);
        #pragma unroll
        for (int nt = 0; nt < 4; nt++) {
            int n = warpN * 32 + nt * 8 + (lane & 3) * 2;
            float a0 = fmaxf(cacc[mt][nt][0] * inv0 + bias0, 0.f);
            float a1 = fmaxf(cacc[mt][nt][1] * inv0 + bias0, 0.f);
            float a2 = fmaxf(cacc[mt][nt][2] * inv1 + bias1, 0.f);
            float a3 = fmaxf(cacc[mt][nt][3] * inv1 + bias1, 0.f);
            op0[n >> 1] = bf2(a0, a1);
            op1[n >> 1] = bf2(a2, a3);
        }
    }
}

// ---------------------------------------------------------------------------
// Kernel 2: corr v6 — direct per-thread island stores (no stage, no per-ky
// syncs), bf16 smem tiles, 4 CTAs/SM.
// word layout (u32): x1[16][8][36] @0, x2[16][14][36] @4608 (cols -4..59),
//   w f32 [16][7][8] @12672 -> 13568 w = 54272 B
// ---------------------------------------------------------------------------
#define C_SMEM 54272
#define CX1W(ce, r)    ((ce) * 288 + (r) * 36)
#define CX2W(ce, row)  (4608 + (ce) * 504 + (row) * 36)
#define CWF(ce, ky, k) (12672 + (ce) * 56 + (ky) * 8 + (k))

__global__ void __launch_bounds__(224, 4) corr_kernel(const float* __restrict__ fw)
{
    extern __shared__ float cs[];
    uint32_t* cw = reinterpret_cast<uint32_t*>(cs);
    const int tid = threadIdx.x;
    const int r   = tid & 7;       // output row within 8-row tile
    const int q   = tid >> 3;      // 0..27
    const int px0 = q * 2;

    const int h0 = blockIdx.x * 8;
    const int tt = blockIdx.y;
    const int b  = blockIdx.z >> 2;
    const int g  = blockIdx.z & 3;
    const int ce0 = g * 16;

    const int t1 = (tt == 0) ? 0 : tt - 1;
    const uint16_t* x1b = g_xencb + (size_t)b * CE * THW + (size_t)t1 * HW;
    const uint16_t* x2b = g_xencb + (size_t)b * CE * THW + (size_t)tt * HW;
    const size_t pixbase = (size_t)b * THW + (size_t)tt * HW + (size_t)h0 * Ww;

    // weights (f32)
    for (int i = tid; i < 16 * 49; i += 224) {
        int ce = i / 49, tap = i % 49;
        cs[CWF(ce, tap / 7, tap % 7)] = fw[((size_t)(ce0 + ce) * Tt + tt) * 49 + tap];
    }
    // x1: 16 ce x 8 rows x 28 words, direct u32 loads
    for (int i = tid; i < 16 * 224; i += 224) {
        int ce = i / 224, rem = i % 224;
        int rr = rem / 28, wi = rem % 28;
        cw[CX1W(ce, rr) + wi] = *reinterpret_cast<const uint32_t*>(
            x1b + (size_t)(ce0 + ce) * THW + (h0 + rr) * Ww + wi * 2);
    }
    // x2 halo: 16 ce x 14 rows x 32 words, cols -4..59; word fully valid or 0
    for (int i = tid; i < 16 * 448; i += 224) {
        int ce = i / 448, rem = i % 448;
        int row = rem / 32, wi = rem % 32;
        int hy = h0 + row - 3;
        int c0 = wi * 2 - 4;
        uint32_t v = 0;
        if (hy >= 0 && hy < Hh && wi >= 2 && wi <= 29)
            v = *reinterpret_cast<const uint32_t*>(
                x2b + (size_t)(ce0 + ce) * THW + hy * Ww + c0);
        cw[CX2W(ce, row) + wi] = v;
    }
    __syncthreads();

    uint16_t* gb0 = g_xcorrb + (pixbase + r * 56 + px0) * KPAD + (size_t)g * 56;

    #pragma unroll 1
    for (int ky = 0; ky < 7; ky++) {
        float acc[7][2];
        #pragma unroll
        for (int kx = 0; kx < 7; kx++) { acc[kx][0] = 0.f; acc[kx][1] = 0.f; }

        const int zr = r + ky;

        #pragma unroll 4
        for (int ce = 0; ce < 16; ce++) {
            uint32_t yv = cw[CX1W(ce, r) + q];
            float y0 = bflo(yv), y1 = bfhi(yv);
            const uint32_t* zp = &cw[CX2W(ce, zr) + q];
            uint32_t zw0 = zp[0], zw1 = zp[1], zw2 = zp[2], zw3 = zp[3], zw4 = zp[4];
            float z[8];
            z[0] = bfhi(zw0);
            z[1] = bflo(zw1); z[2] = bfhi(zw1);
            z[3] = bflo(zw2); z[4] = bfhi(zw2);
            z[5] = bflo(zw3); z[6] = bfhi(zw3);
            z[7] = bflo(zw4);
            const float* wp = &cs[CWF(ce, ky, 0)];
            float4 w4 = *reinterpret_cast<const float4*>(wp);
            float2 w2 = *reinterpret_cast<const float2*>(wp + 4);
            float  w6 = wp[6];
            float w[7] = {w4.x, w4.y, w4.z, w4.w, w2.x, w2.y, w6};
            #pragma unroll
            for (int kx = 0; kx < 7; kx++) {
                acc[kx][0] += w[kx] * (y0 * z[kx]);
                acc[kx][1] += w[kx] * (y1 * z[kx + 1]);
            }
        }

        // direct island stores: one uint4 per owned pixel
        const float sc = 1.f / 16.f;
        uint4 v;
        v.x = bf2(acc[0][0] * sc, acc[1][0] * sc);
        v.y = bf2(acc[2][0] * sc, acc[3][0] * sc);
        v.z = bf2(acc[4][0] * sc, acc[5][0] * sc);
        v.w = bf2(acc[6][0] * sc, 0.f);
        *reinterpret_cast<uint4*>(gb0 + ky * 8) = v;
        v.x = bf2(acc[0][1] * sc, acc[1][1] * sc);
        v.y = bf2(acc[2][1] * sc, acc[3][1] * sc);
        v.z = bf2(acc[4][1] * sc, acc[5][1] * sc);
        v.w = bf2(acc[6][1] * sc, 0.f);
        *reinterpret_cast<uint4*>(gb0 + KPAD + ky * 8) = v;
    }
}

// ---------------------------------------------------------------------------
// Kernel 3: dec GEMM bf16 mma + ldmatrix, 2-stage B pipeline + x-residual
// smem prefetch (interleaved cp.async). BM=128, BN=128, 256 thr, 2 CTAs/SM.
// smem: stage s: A 8KB + B 8KB at s*16384; x tile f32 [128][136] @32768.
// ---------------------------------------------------------------------------
#define D_SMEM (32768 + 69632)    // 102400
#define D_AST(s) ((s) * 16384)
#define D_BST(s) ((s) * 16384 + 8192)
#define D_XST   32768

__global__ void __launch_bounds__(256, 2) dec_kernel(
    const float* __restrict__ x,
    const float* __restrict__ dg, const float* __restrict__ db,
    const float* __restrict__ dm, const float* __restrict__ dv,
    float* __restrict__ out)
{
    extern __shared__ char dsm[];
    const int t    = threadIdx.x;
    const int wid  = t >> 5, lane = t & 31;
    const int warpM = wid >> 2;
    const int warpN = wid & 3;

    const int nx = blockIdx.x >> 1;
    const int m0 = (blockIdx.x & 1) * 128;
    const int b  = blockIdx.y;
    const size_t nbase = (size_t)nx * 128;

    const uint16_t* arow = g_dwb + (size_t)m0 * KPAD;
    const uint16_t* brow = g_xcorrb + ((size_t)b * THW + nbase) * KPAD;
    const float*    xrow = x + ((size_t)b * Cc + m0) * THW + nbase;

    float cacc[4][4][4];
    #pragma unroll
    for (int i = 0; i < 4; i++)
        #pragma unroll
        for (int j = 0; j < 4; j++)
            #pragma unroll
            for (int r = 0; r < 4; r++) cacc[i][j][r] = 0.f;

    const int rowBl = warpN * 32 + lane;
    const int swzB  = ((rowBl >> 1) & 3) << 2;
    const int rAoff = (lane & 7) + ((lane >> 3) & 1) * 8;
    const int khA   = ((lane >> 4) & 1) * 4;

    auto load_chunk = [&](int kc, int s) {
        #pragma unroll
        for (int i = 0; i < 2; i++) {
            int e = t + 256 * i;
            int row = e >> 2, c = e & 3;
            uint32_t soff = row * 64 + ((c ^ ((row >> 1) & 3)) << 4);
            cp_async16(smem_u32(dsm + D_AST(s) + soff),
                       arow + (size_t)row * KPAD + kc * 32 + c * 8, 16);
            cp_async16(smem_u32(dsm + D_BST(s) + soff),
                       brow + (size_t)row * KPAD + kc * 32 + c * 8, 16);
        }
        // x-residual prefetch portion kc (16 chunks/thread over 7 portions)
        for (int j = kc; j < 16; j += 7) {
            int e = j * 256 + t;
            int row = e >> 5, cwd = (e & 31) * 4;
            cp_async16(smem_u32(dsm + D_XST + (row * 136 + cwd) * 4),
                       xrow + (size_t)row * THW + cwd, 16);
        }
    };

    load_chunk(0, 0);
    cp_commit();

    for (int c = 0; c < 7; c++) {
        const int s = c & 1;
        if (c > 0) __syncthreads();
        if (c + 1 < 7) { load_chunk(c + 1, s ^ 1); cp_commit(); cp_wait1(); }
        else cp_wait0();
        __syncthreads();

        const uint32_t* Ab = reinterpret_cast<const uint32_t*>(dsm + D_AST(s));
        const uint32_t* Bb = reinterpret_cast<const uint32_t*>(dsm + D_BST(s));

        #pragma unroll
        for (int ks = 0; ks < 2; ks++) {
            const int kb = ks * 8;
            uint32_t bh0[4], bh1[4];
            ldsm_x4(bh0, smem_u32(Bb + rowBl * 16 + (kb ^ swzB)));
            ldsm_x4(bh1, smem_u32(Bb + rowBl * 16 + ((kb + 4) ^ swzB)));
            #pragma unroll
            for (int mt = 0; mt < 4; mt++) {
                int rowA = warpM * 64 + mt * 16 + rAoff;
                int wA = (kb + khA) ^ (((rowA >> 1) & 3) << 2);
                uint32_t afr[4];
                ldsm_x4(afr, smem_u32(Ab + rowA * 16 + wA));
                #pragma unroll
                for (int nt = 0; nt < 4; nt++) {
                    uint32_t bfr[2] = {bh0[nt], bh1[nt]};
                    mma_bf16(cacc[mt][nt], afr, bfr);
                }
            }
        }
    }

    // Epilogue: BN + residual (from smem) + ReLU
    const float* xs = reinterpret_cast<const float*>(dsm + D_XST);
    #pragma unroll
    for (int mt = 0; mt < 4; mt++) {
        int lr0  = warpM * 64 + mt * 16 + (lane >> 2);
        int mrow = m0 + lr0;
        float inv0  = dg[mrow] * rsqrtf(dv[mrow] + EPSI);
        float bias0 = db[mrow] - dm[mrow] * inv0;
        float inv1  = dg[mrow + 8] * rsqrtf(dv[mrow + 8] + EPSI);
        float bias1 = db[mrow + 8] - dm[mrow + 8] * inv1;
        float* op0 = out + ((size_t)b * Cc + mrow)     * THW + nbase;
        float* op1 = out + ((size_t)b * Cc + mrow + 8) * THW + nbase;
        #pragma unroll
        for (int nt = 0; nt < 4; nt++) {
            int n = warpN * 32 + nt * 8 + (lane & 3) * 2;
            float2 r0 = *reinterpret_cast<const float2*>(xs + lr0 * 136 + n);
            float2 r1 = *reinterpret_cast<const float2*>(xs + (lr0 + 8) * 136 + n);
            float2 o0, o1;
            o0.x = fmaxf(cacc[mt][nt][0] * inv0 + bias0 + r0.x, 0.f);
            o0.y = fmaxf(cacc[mt][nt][1] * inv0 + bias0 + r0.y, 0.f);
            o1.x = fmaxf(cacc[mt][nt][2] * inv1 + bias1 + r1.x, 0.f);
            o1.y = fmaxf(cacc[mt][nt][3] * inv1 + bias1 + r1.y, 0.f);
            *reinterpret_cast<float2*>(op0 + n) = o0;
            *reinterpret_cast<float2*>(op1 + n) = o1;
        }
    }
}

// ---------------------------------------------------------------------------
extern "C" void kernel_launch(void* const* d_in, const int* in_sizes, int n_in,
                              void* d_out, int out_size)
{
    const float* x     = (const float*)d_in[0];
    const float* enc_w = (const float*)d_in[1];
    const float* eg    = (const float*)d_in[2];
    const float* eb    = (const float*)d_in[3];
    const float* em    = (const float*)d_in[4];
    const float* ev    = (const float*)d_in[5];
    const float* fw    = (const float*)d_in[6];
    const float* dw    = (const float*)d_in[7];
    const float* dg    = (const float*)d_in[8];
    const float* db    = (const float*)d_in[9];
    const float* dm    = (const float*)d_in[10];
    const float* dv    = (const float*)d_in[11];
    float* out = (float*)d_out;

    cudaFuncSetAttribute(enc_kernel,
                         cudaFuncAttributeMaxDynamicSharedMemorySize, E_SMEM);
    cudaFuncSetAttribute(corr_kernel,
                         cudaFuncAttributeMaxDynamicSharedMemorySize, C_SMEM);
    cudaFuncSetAttribute(dec_kernel,
                         cudaFuncAttributeMaxDynamicSharedMemorySize, D_SMEM);

    int prep_n = Cc * KPAD + CE * Cc;
    prep_kernel<<<(prep_n + 255) / 256, 256>>>(dw, enc_w);

    dim3 g1(THW / 256, Bsz);
    enc_kernel<<<g1, 256, E_SMEM>>>(x, eg, eb, em, ev);

    dim3 g2(Hh / 8, Tt, Bsz * Gg);
    corr_kernel<<<g2, 224, C_SMEM>>>(fw);

    dim3 g3(THW / 128 * 2, Bsz);
    dec_kernel<<<g3, 256, D_SMEM>>>(x, dg, db, dm, dv, out);
}